// round 12
// baseline (speedup 1.0000x reference)
#include <cuda_runtime.h>
#include <cuda_fp16.h>
#include <math.h>
#include <stdint.h>

// Problem constants
#define B_ 2
#define L_ 2048
#define D_ 2048
#define H_ 8
#define HD_ 256
#define FD_ 64
#define FEAT_ 128          // 2*FD
#define CHUNK_ 64
#define NCH_ (L_/CHUNK_)   // 32
#define HALF_ (HD_/2)      // 128

// ---------------- scratch (device globals; no allocation allowed) ----------
__device__ float g_q [B_*L_*H_*HD_];
__device__ float g_k [B_*L_*HD_];
__device__ float g_v [B_*L_*HD_];
__device__ float g_qf[B_*H_*L_*FEAT_];
__device__ float g_kf[B_*H_*L_*FEAT_];
__device__ float g_kv[B_*H_*NCH_*FEAT_*HD_];

__device__ __half g_hh[B_*L_*D_];
__device__ __half g_oh[B_*L_*H_*HD_];
__device__ __half g_wqh[D_*H_*HD_];
__device__ __half g_wkh[HD_*D_];
__device__ __half g_wvh[HD_*D_];
__device__ __half g_woh[D_*H_*HD_];

// ---------------- helpers ---------------------------------------------------
__device__ __forceinline__ void mma_f16(float* d,
                                        const uint32_t* a,
                                        const uint32_t* b) {
    asm volatile(
        "mma.sync.aligned.m16n8k16.row.col.f32.f16.f16.f32 "
        "{%0,%1,%2,%3}, {%4,%5,%6,%7}, {%8,%9}, {%0,%1,%2,%3};\n"
        : "+f"(d[0]), "+f"(d[1]), "+f"(d[2]), "+f"(d[3])
        : "r"(a[0]), "r"(a[1]), "r"(a[2]), "r"(a[3]),
          "r"(b[0]), "r"(b[1]));
}
__device__ __forceinline__ void cp16s(uint32_t saddr, const void* g) {
    asm volatile("cp.async.cg.shared.global [%0], [%1], 16;\n"
                 :: "r"(saddr), "l"(g));
}
__device__ __forceinline__ void cp_commit() {
    asm volatile("cp.async.commit_group;\n");
}
__device__ __forceinline__ void ldsm4(uint32_t* r, uint32_t saddr) {
    asm volatile("ldmatrix.sync.aligned.m8n8.x4.shared.b16 {%0,%1,%2,%3}, [%4];\n"
                 : "=r"(r[0]), "=r"(r[1]), "=r"(r[2]), "=r"(r[3]) : "r"(saddr));
}

// ---------------- convert kernels ------------------------------------------
__global__ __launch_bounds__(256)
void cvt_kernel(const float* __restrict__ x, __half* __restrict__ hi,
                int off, int n) {
    int i = off + (blockIdx.x*256 + threadIdx.x)*8;
    if (i >= off + n) return;
    float4 a = *(const float4*)(x + i);
    float4 b = *(const float4*)(x + i + 4);
    __half2* o = (__half2*)(hi + i);
    o[0] = __floats2half2_rn(a.x, a.y);
    o[1] = __floats2half2_rn(a.z, a.w);
    o[2] = __floats2half2_rn(b.x, b.y);
    o[3] = __floats2half2_rn(b.z, b.w);
}

// All four weight transposes in one launch. z: 0=Wq, 1=Wo, 2=Wk, 3=Wv.
__global__ __launch_bounds__(256)
void splitT_all_kernel(const float* __restrict__ Wq, __half* tq,
                       const float* __restrict__ Wo, __half* to,
                       const float* __restrict__ Wk, __half* tk,
                       const float* __restrict__ Wv, __half* tv) {
    int z = blockIdx.z;
    const float* W; __half* th; int K, N;
    if      (z == 0) { W = Wq; th = tq; K = D_;     N = H_*HD_; }
    else if (z == 1) { W = Wo; th = to; K = H_*HD_; N = D_;     }
    else if (z == 2) { W = Wk; th = tk; K = D_;     N = HD_;    }
    else             { W = Wv; th = tv; K = D_;     N = HD_;    }
    int n0 = blockIdx.x*32, k0 = blockIdx.y*32;
    if (n0 >= N || k0 >= K) return;
    __shared__ float tile[32][33];
    int tx = threadIdx.x & 31, ty = threadIdx.x >> 5;
    #pragma unroll
    for (int r = 0; r < 32; r += 8)
        tile[ty + r][tx] = W[(size_t)(k0 + ty + r)*N + n0 + tx];
    __syncthreads();
    #pragma unroll
    for (int r = 0; r < 32; r += 8) {
        float v = tile[tx][ty + r];
        th[(size_t)(n0 + ty + r)*K + k0 + tx] = __float2half_rn(v);
    }
}

// ============================================================================
// hgemm: single-term fp16 GEMM, block 128x256x16, 8 warps (2x4), warp 64x64.
// 5-stage cp.async.cg pipeline + ldmatrix. A fp16 [M,K]; B fp16 T [N,K].
// grid.x: [0,nq) -> Q (N=qN), [nq,nq+nk) -> K (N=256), rest -> V (N=256).
// ============================================================================
#define LDWW 12               // words per 16-half row (8 data + 4 pad)
#define ASECW (128*LDWW)      // 1536 words
#define BSECW (256*LDWW)      // 3072 words
#define STW  (ASECW + BSECW)  // 4608 words per stage
#define NSTG 5
#define SMEM_BYTES (NSTG*STW*4)   // 92160

__global__ __launch_bounds__(256, 1)
void hgemm_kernel(int M, int K, int nq, int nk,
                  const __half* __restrict__ Ah,
                  const __half* __restrict__ qBh, float* __restrict__ qC, int qN,
                  const __half* __restrict__ kBh, float* __restrict__ kC,
                  const __half* __restrict__ vBh, float* __restrict__ vC) {
    extern __shared__ uint32_t smem[];
    const uint32_t smem_u32 = (uint32_t)__cvta_generic_to_shared(smem);

    const int cx = blockIdx.x;
    const __half* Bh;
    float* C;
    int N, ccol;
    if (cx < nq)           { Bh = qBh; C = qC; N = qN;  ccol = cx; }
    else if (cx < nq + nk) { Bh = kBh; C = kC; N = 256; ccol = cx - nq; }
    else                   { Bh = vBh; C = vC; N = 256; ccol = cx - nq - nk; }

    const int tid = threadIdx.x, lane = tid & 31, warp = tid >> 5;
    const int warpM = warp & 1, warpN = warp >> 1;   // 2 x 4, warp tile 64x64
    const int cRow = blockIdx.y;

    // copy mapping: A 1 chunk, B 2 chunks (rows row, row+128)
    const int row = tid >> 1, half = tid & 1;
    const __half* aP  = Ah + (size_t)(cRow*128 + row)*K + half*8;
    const __half* bP0 = Bh + (size_t)(ccol*256 + row)*K + half*8;
    const __half* bP1 = Bh + (size_t)(ccol*256 + row + 128)*K + half*8;
    const uint32_t adst = row*LDWW + half*4;
    const uint32_t bdst0 = ASECW + row*LDWW + half*4;
    const uint32_t bdst1 = ASECW + (row + 128)*LDWW + half*4;

    const int l7 = lane & 7;
    const uint32_t aoffw = (uint32_t)((warpM*64 + l7 + ((lane>>3)&1)*8)*LDWW + (lane>>4)*4);
    uint32_t boffw[4];
    #pragma unroll
    for (int p = 0; p < 4; p++)
        boffw[p] = (uint32_t)(ASECW +
            (warpN*64 + p*16 + l7 + ((lane>>4)&1)*8)*LDWW + ((lane>>3)&1)*4);

    float acc[4][8][4];
    #pragma unroll
    for (int mt = 0; mt < 4; mt++)
        #pragma unroll
        for (int nt = 0; nt < 8; nt++)
            #pragma unroll
            for (int i = 0; i < 4; i++) acc[mt][nt][i] = 0.f;

    const int KT = K >> 4;

    // prologue: stages 0..3
    #pragma unroll
    for (int s = 0; s < NSTG - 1; s++) {
        const int ko = s*16;
        const uint32_t sb = smem_u32 + (s*STW)*4;
        cp16s(sb + adst*4,  aP  + ko);
        cp16s(sb + bdst0*4, bP0 + ko);
        cp16s(sb + bdst1*4, bP1 + ko);
        cp_commit();
    }

    int sc = 0;
    for (int kt = 0; kt < KT; kt++) {
        if (kt < KT - 3)      { asm volatile("cp.async.wait_group 3;\n"); }
        else if (kt < KT - 2) { asm volatile("cp.async.wait_group 2;\n"); }
        else if (kt < KT - 1) { asm volatile("cp.async.wait_group 1;\n"); }
        else                  { asm volatile("cp.async.wait_group 0;\n"); }
        __syncthreads();

        if (kt + NSTG - 1 < KT) {
            int sl = sc + (NSTG - 1); if (sl >= NSTG) sl -= NSTG;
            const int ko = (kt + NSTG - 1)*16;
            const uint32_t sb = smem_u32 + (sl*STW)*4;
            cp16s(sb + adst*4,  aP  + ko);
            cp16s(sb + bdst0*4, bP0 + ko);
            cp16s(sb + bdst1*4, bP1 + ko);
            cp_commit();
        }

        const uint32_t sb = smem_u32 + (sc*STW)*4;

        uint32_t bhf[4][4];
        #pragma unroll
        for (int p = 0; p < 4; p++)
            ldsm4(bhf[p], sb + boffw[p]*4);

        #pragma unroll
        for (int mt = 0; mt < 4; mt++) {
            uint32_t ahf[4];
            ldsm4(ahf, sb + (aoffw + mt*16*LDWW)*4);
            #pragma unroll
            for (int nt = 0; nt < 8; nt++) {
                const uint32_t* bp = &bhf[nt >> 1][(nt & 1)*2];
                mma_f16(acc[mt][nt], ahf, bp);
            }
        }
        sc = (sc + 1 == NSTG) ? 0 : sc + 1;
    }

    const int g = lane >> 2, t4 = lane & 3;
    float* Cb = C + (size_t)cRow*128*N + ccol*256;
    #pragma unroll
    for (int mt = 0; mt < 4; mt++) {
        const int r0 = warpM*64 + mt*16 + g;
        #pragma unroll
        for (int nt = 0; nt < 8; nt++) {
            const int c = warpN*64 + nt*8 + t4*2;
            *(float2*)&Cb[(size_t)r0 * N + c]       = make_float2(acc[mt][nt][0], acc[mt][nt][1]);
            *(float2*)&Cb[(size_t)(r0 + 8) * N + c] = make_float2(acc[mt][nt][2], acc[mt][nt][3]);
        }
    }
}

// ============================================================================
// hedgehog2 (unchanged from R10 — measured 54us/call)
// ============================================================================
#define XS_STRIDE 260
#define FS_STRIDE 68
#define HG_SMEM ((64*XS_STRIDE + 64*FS_STRIDE + 128)*4)

__global__ __launch_bounds__(256, 2)
void hedgehog2_kernel(const float* __restrict__ x,
                      const float* __restrict__ cs,
                      const float* __restrict__ sn,
                      const float* __restrict__ fm,
                      float* __restrict__ outf,
                      int xh, float scale) {
    extern __shared__ float sm[];
    float* xs = sm;
    float* fs = sm + 64*XS_STRIDE;
    float* mz = fs + 64*FS_STRIDE;

    const int h = blockIdx.y, b = blockIdx.z;
    const int l0 = blockIdx.x * 64;
    const int t = threadIdx.x;
    const int srcH = (xh == 1) ? 0 : h;

    const float* xb = x + ((size_t)(b*L_ + l0)*xh + srcH)*HD_;
    const size_t xstride = (size_t)xh*HD_;
    #pragma unroll
    for (int p = 0; p < 16; p++) {
        int idx4 = p*256 + t;
        int r = idx4 >> 6, c4 = idx4 & 63;
        float4 v = *(const float4*)&xb[r*xstride + c4*4];
        *(float4*)&xs[r*XS_STRIDE + c4*4] = v;
    }
    __syncthreads();

    #pragma unroll
    for (int p = 0; p < 32; p++) {
        int e = p*256 + t;
        int r = e >> 7, j = e & 127;
        float c = cs[(l0 + r)*HALF_ + j];
        float s = sn[(l0 + r)*HALF_ + j];
        float x1 = xs[r*XS_STRIDE + j], x2 = xs[r*XS_STRIDE + j + 128];
        xs[r*XS_STRIDE + j]       = x1*c - x2*s;
        xs[r*XS_STRIDE + j + 128] = x1*s + x2*c;
    }
    __syncthreads();

    const int tr = t >> 4, tc = t & 15;
    float acc[4][4];
    #pragma unroll
    for (int i = 0; i < 4; i++)
        #pragma unroll
        for (int j = 0; j < 4; j++) acc[i][j] = 0.f;

    const float* fmh = fm + (size_t)h*HD_*FD_;
    for (int dt = 0; dt < 4; dt++) {
        #pragma unroll
        for (int p = 0; p < 4; p++) {
            int idx4 = p*256 + t;
            int r = idx4 >> 4, c4 = idx4 & 15;
            float4 v = *(const float4*)&fmh[(size_t)(dt*64 + r)*FD_ + c4*4];
            *(float4*)&fs[r*FS_STRIDE + c4*4] = v;
        }
        __syncthreads();

        #pragma unroll 4
        for (int dd = 0; dd < 64; dd += 4) {
            float4 xv[4], fv[4];
            #pragma unroll
            for (int i = 0; i < 4; i++)
                xv[i] = *(const float4*)&xs[(tr*4 + i)*XS_STRIDE + dt*64 + dd];
            #pragma unroll
            for (int k = 0; k < 4; k++)
                fv[k] = *(const float4*)&fs[(dd + k)*FS_STRIDE + tc*4];
            #pragma unroll
            for (int i = 0; i < 4; i++) {
                float* fvp0 = (float*)&fv[0];
                float* fvp1 = (float*)&fv[1];
                float* fvp2 = (float*)&fv[2];
                float* fvp3 = (float*)&fv[3];
                #pragma unroll
                for (int j = 0; j < 4; j++)
                    acc[i][j] += xv[i].x*fvp0[j] + xv[i].y*fvp1[j]
                               + xv[i].z*fvp2[j] + xv[i].w*fvp3[j];
            }
        }
        __syncthreads();
    }

    #pragma unroll
    for (int i = 0; i < 4; i++)
        *(float4*)&fs[(tr*4 + i)*FS_STRIDE + tc*4] =
            make_float4(acc[i][0], acc[i][1], acc[i][2], acc[i][3]);
    __syncthreads();

    const int warp = t >> 5, lane = t & 31;
    for (int rr = 0; rr < 8; rr++) {
        int rowi = warp*8 + rr;
        float v0 = fs[rowi*FS_STRIDE + lane];
        float v1 = fs[rowi*FS_STRIDE + lane + 32];
        float m = fmaxf(fabsf(v0), fabsf(v1));
        #pragma unroll
        for (int off = 16; off > 0; off >>= 1)
            m = fmaxf(m, __shfl_xor_sync(0xFFFFFFFF, m, off));
        float z = __expf(v0 - m) + __expf(-v0 - m)
                + __expf(v1 - m) + __expf(-v1 - m);
        #pragma unroll
        for (int off = 16; off > 0; off >>= 1)
            z += __shfl_xor_sync(0xFFFFFFFF, z, off);
        if (lane == 0) { mz[rowi] = m; mz[64 + rowi] = z; }
    }
    __syncthreads();

    float* ob = outf + ((size_t)(b*H_ + h)*L_ + l0)*FEAT_;
    #pragma unroll
    for (int p = 0; p < 8; p++) {
        int idx4 = p*256 + t;
        int rowi = idx4 >> 5, c4 = idx4 & 31;
        int f = c4*4;
        float m = mz[rowi], z = mz[64 + rowi];
        float inv = scale / z;
        float4 pv;
        if (f < 64) {
            pv = *(const float4*)&fs[rowi*FS_STRIDE + f];
            pv.x = __expf(pv.x - m)*inv; pv.y = __expf(pv.y - m)*inv;
            pv.z = __expf(pv.z - m)*inv; pv.w = __expf(pv.w - m)*inv;
        } else {
            pv = *(const float4*)&fs[rowi*FS_STRIDE + f - 64];
            pv.x = __expf(-pv.x - m)*inv; pv.y = __expf(-pv.y - m)*inv;
            pv.z = __expf(-pv.z - m)*inv; pv.w = __expf(-pv.w - m)*inv;
        }
        *(float4*)&ob[(size_t)rowi*FEAT_ + f] = pv;
    }
}

// ============================================================================
// kvcum: fused per-chunk kv state + EXCLUSIVE cumsum.
// Block (ft, dh, bh) owns a 64f x 128d tile and walks chunks n=0..31:
//   write current prefix (exclusive), then accumulate chunk n in registers.
// grid (2, 2, 16) = 64 blocks; thread tile 4f x 8d.
// ============================================================================
__global__ __launch_bounds__(256)
void kvcum_kernel(const float* __restrict__ kf, const float* __restrict__ v,
                  float* __restrict__ kv) {
    __shared__ float ks[32][64];    // 8 KB
    __shared__ float vs[32][128];   // 16 KB
    const int ft = blockIdx.x;      // f half (64 wide)
    const int dh = blockIdx.y;      // d half (128 wide)
    const int bh = blockIdx.z;
    const int b  = bh / H_;
    const int t  = threadIdx.x;
    const int tf = t >> 4;          // 0..15 -> f rows tf*4..tf*4+3 (within 64)
    const int td = t & 15;          // d cols td*4, 64+td*4

    const float* kfb = kf + ((size_t)bh*L_)*FEAT_ + ft*64;
    const float* vb  = v  + ((size_t)b*L_)*HD_ + dh*128;

    float acc[4][8];
    #pragma unroll
    for (int i = 0; i < 4; i++)
        #pragma unroll
        for (int j = 0; j < 8; j++) acc[i][j] = 0.f;

    for (int n = 0; n < NCH_; n++) {
        // write exclusive prefix for chunk n
        float* out = kv + ((size_t)(bh*NCH_ + n)*FEAT_ + ft*64)*HD_ + dh*128;
        #pragma unroll
        for (int i = 0; i < 4; i++) {
            size_t ro = (size_t)(tf*4 + i)*HD_;
            *(float4*)&out[ro + td*4]      = make_float4(acc[i][0], acc[i][1], acc[i][2], acc[i][3]);
            *(float4*)&out[ro + 64 + td*4] = make_float4(acc[i][4], acc[i][5], acc[i][6], acc[i][7]);
        }

        // accumulate chunk n
        for (int cc = 0; cc < 2; cc++) {
            const int r0 = n*CHUNK_ + cc*32;
            #pragma unroll
            for (int i = 0; i < 2; i++) {
                int e = i*256 + t;
                int r = e >> 4, c4 = e & 15;
                *(float4*)&ks[r][c4*4] = *(const float4*)&kfb[(size_t)(r0 + r)*FEAT_ + c4*4];
            }
            #pragma unroll
            for (int i = 0; i < 4; i++) {
                int e = i*256 + t;
                int r = e >> 5, c4 = e & 31;
                *(float4*)&vs[r][c4*4] = *(const float4*)&vb[(size_t)(r0 + r)*HD_ + c4*4];
            }
            __syncthreads();

            #pragma unroll 4
            for (int c = 0; c < 32; c++) {
                float4 ka = *(const float4*)&ks[c][tf*4];
                float4 va = *(const float4*)&vs[c][td*4];
                float4 vb2 = *(const float4*)&vs[c][64 + td*4];
                float kk[4] = {ka.x, ka.y, ka.z, ka.w};
                float vv[8] = {va.x,va.y,va.z,va.w,vb2.x,vb2.y,vb2.z,vb2.w};
                #pragma unroll
                for (int i = 0; i < 4; i++)
                    #pragma unroll
                    for (int j = 0; j < 8; j++)
                        acc[i][j] += kk[i]*vv[j];
            }
            __syncthreads();
        }
    }
}

// ---------------- inter + intra chunk attention (fp16 half2 output) -------
__global__ __launch_bounds__(256)
void attn_kernel(const float* __restrict__ qf, const float* __restrict__ kf,
                 const float* __restrict__ v,  const float* __restrict__ kv,
                 __half* __restrict__ oh) {
    __shared__ float qs[CHUNK_][FEAT_];
    __shared__ float ss[CHUNK_][CHUNK_];
    int n = blockIdx.x, h = blockIdx.y, b = blockIdx.z;
    int bh = b*H_ + h;
    int t = threadIdx.x;
    const int c2 = (t & 127) * 2;
    const int rh = t >> 7;

    const float* qp = qf + ((size_t)bh*L_ + n*CHUNK_)*FEAT_;
    for (int e = t; e < CHUNK_*FEAT_; e += 256) qs[e/FEAT_][e%FEAT_] = qp[e];
    __syncthreads();

    float acc[32][2];
    #pragma unroll
    for (int i = 0; i < 32; i++) { acc[i][0] = 0.f; acc[i][1] = 0.f; }

    const float* kvp = kv + ((size_t)(bh*NCH_ + n)*FEAT_)*HD_;
    for (int f = 0; f < FEAT_; f += 4) {
        float2 k0 = *(const float2*)&kvp[(size_t)(f+0)*HD_ + c2];
        float2 k1 = *(const float2*)&kvp[(size_t)(f+1)*HD_ + c2];
        float2 k2 = *(const float2*)&kvp[(size_t)(f+2)*HD_ + c2];
        float2 k3 = *(const float2*)&kvp[(size_t)(f+3)*HD_ + c2];
        #pragma unroll
        for (int i = 0; i < 32; i++) {
            float4 qv = *(const float4*)&qs[rh*32 + i][f];
            acc[i][0] += qv.x*k0.x + qv.y*k1.x + qv.z*k2.x + qv.w*k3.x;
            acc[i][1] += qv.x*k0.y + qv.y*k1.y + qv.z*k2.y + qv.w*k3.y;
        }
    }

    {
        const float* kp = kf + ((size_t)bh*L_ + n*CHUNK_)*FEAT_;
        int i   = t / 4;
        int jp0 = (t % 4) * 16;
        for (int jj = 0; jj < 16; jj++) {
            int jp = jp0 + jj;
            float sum = 0.f;
            if (jp <= i) {
                const float* krow = kp + (size_t)jp*FEAT_;
                #pragma unroll 8
                for (int f = 0; f < FEAT_; f += 4) {
                    float4 qv = *(const float4*)&qs[i][f];
                    float4 kr = *(const float4*)&krow[f];
                    sum += qv.x*kr.x + qv.y*kr.y + qv.z*kr.z + qv.w*kr.w;
                }
            }
            ss[i][jp] = sum;
        }
    }
    __syncthreads();

    const float* vp = v + ((size_t)b*L_ + n*CHUNK_)*HD_;
    for (int jp = 0; jp < CHUNK_; jp += 4) {
        float2 v0 = *(const float2*)&vp[(size_t)(jp+0)*HD_ + c2];
        float2 v1 = *(const float2*)&vp[(size_t)(jp+1)*HD_ + c2];
        float2 v2 = *(const float2*)&vp[(size_t)(jp+2)*HD_ + c2];
        float2 v3 = *(const float2*)&vp[(size_t)(jp+3)*HD_ + c2];
        #pragma unroll
        for (int i = 0; i < 32; i++) {
            float4 sv = *(const float4*)&ss[rh*32 + i][jp];
            acc[i][0] += sv.x*v0.x + sv.y*v1.x + sv.z*v2.x + sv.w*v3.x;
            acc[i][1] += sv.x*v0.y + sv.y*v1.y + sv.z*v2.y + sv.w*v3.y;
        }
    }

    __half* op = oh + ((size_t)(b*L_ + n*CHUNK_ + rh*32))*(H_*HD_) + h*HD_ + c2;
    #pragma unroll
    for (int i = 0; i < 32; i++)
        *(__half2*)&op[(size_t)i*(H_*HD_)] = __floats2half2_rn(acc[i][0], acc[i][1]);
}

// ---------------- launch ---------------------------------------------------
extern "C" void kernel_launch(void* const* d_in, const int* in_sizes, int n_in,
                              void* d_out, int out_size) {
    const float* hidden = (const float*)d_in[0];
    const float* fcos   = (const float*)d_in[1];
    const float* fsin   = (const float*)d_in[2];
    // d_in[3] = mask (unused)
    const float* Wq     = (const float*)d_in[4];
    const float* Wk     = (const float*)d_in[5];
    const float* Wv     = (const float*)d_in[6];
    const float* Wo     = (const float*)d_in[7];
    const float* fmq    = (const float*)d_in[8];
    const float* fmk    = (const float*)d_in[9];
    float* out          = (float*)d_out;

    float *q, *k, *v, *qf, *kf, *kv;
    cudaGetSymbolAddress((void**)&q,  g_q);
    cudaGetSymbolAddress((void**)&k,  g_k);
    cudaGetSymbolAddress((void**)&v,  g_v);
    cudaGetSymbolAddress((void**)&qf, g_qf);
    cudaGetSymbolAddress((void**)&kf, g_kf);
    cudaGetSymbolAddress((void**)&kv, g_kv);

    __half *hh,*oh,*wqh,*wkh,*wvh,*woh;
    cudaGetSymbolAddress((void**)&hh,  g_hh);
    cudaGetSymbolAddress((void**)&oh,  g_oh);
    cudaGetSymbolAddress((void**)&wqh, g_wqh);
    cudaGetSymbolAddress((void**)&wkh, g_wkh);
    cudaGetSymbolAddress((void**)&wvh, g_wvh);
    cudaGetSymbolAddress((void**)&woh, g_woh);

    cudaFuncSetAttribute(hgemm_kernel,
                         cudaFuncAttributeMaxDynamicSharedMemorySize, SMEM_BYTES);
    cudaFuncSetAttribute(hedgehog2_kernel,
                         cudaFuncAttributeMaxDynamicSharedMemorySize, HG_SMEM);

    const int M = B_*L_;   // 4096
    const float qscale = 0.08838834764831845f;   // 128^-0.5
    const int halfN = (M*D_)/2;

    // 0: all weight transposes
    splitT_all_kernel<<<dim3(64, 64, 4), 256>>>(Wq, wqh, Wo, woh, Wk, wkh, Wv, wvh);
    // 1,2: convert hidden -> fp16 (two halves)
    cvt_kernel<<<halfN/2048, 256>>>(hidden, hh, 0,     halfN);
    cvt_kernel<<<halfN/2048, 256>>>(hidden, hh, halfN, halfN);
    // 3: fused Q+K+V projections (PROFILED slot); Q: 8 col blocks, K: 1, V: 1
    hgemm_kernel<<<dim3(10, M/128), 256, SMEM_BYTES>>>(M, D_, 8, 1,
        hh, wqh, q, H_*HD_, wkh, k, wvh, v);
    // 4: hedgehog q (fused RoPE)
    hedgehog2_kernel<<<dim3(L_/64, H_, B_), 256, HG_SMEM>>>(q, fcos, fsin, fmq, qf, H_, qscale);
    // 5: hedgehog k
    hedgehog2_kernel<<<dim3(L_/64, H_, B_), 256, HG_SMEM>>>(k, fcos, fsin, fmk, kf, 1, 1.0f);
    // 6: fused kv states + exclusive cumsum
    kvcum_kernel<<<dim3(2, 2, B_*H_), 256>>>(kf, v, kv);
    // 7: inter + intra attention -> fp16 oh
    attn_kernel<<<dim3(NCH_, H_, B_), 256>>>(qf, kf, v, kv, oh);
    // 8: output projection (N=2048 -> 8 col blocks)
    hgemm_kernel<<<dim3(8, M/128), 256, SMEM_BYTES>>>(M, H_*HD_, 8, 0,
        oh, woh, out, D_, woh, out, woh, out);
}

// round 13
// speedup vs baseline: 1.2331x; 1.2331x over previous
#include <cuda_runtime.h>
#include <cuda_fp16.h>
#include <math.h>
#include <stdint.h>

// Problem constants
#define B_ 2
#define L_ 2048
#define D_ 2048
#define H_ 8
#define HD_ 256
#define FD_ 64
#define FEAT_ 128          // 2*FD
#define CHUNK_ 64
#define NCH_ (L_/CHUNK_)   // 32
#define HALF_ (HD_/2)      // 128

// ---------------- scratch (device globals; no allocation allowed) ----------
__device__ float g_q [B_*L_*H_*HD_];
__device__ float g_k [B_*L_*HD_];
__device__ float g_v [B_*L_*HD_];
__device__ float g_qf[B_*H_*L_*FEAT_];
__device__ float g_kf[B_*H_*L_*FEAT_];
__device__ float g_kv[B_*H_*NCH_*FEAT_*HD_];

__device__ __half g_hh[B_*L_*D_];
__device__ __half g_oh[B_*L_*H_*HD_];
__device__ __half g_wqh[D_*H_*HD_];
__device__ __half g_wkh[HD_*D_];
__device__ __half g_wvh[HD_*D_];
__device__ __half g_woh[D_*H_*HD_];

// ---------------- helpers ---------------------------------------------------
__device__ __forceinline__ void mma_f16(float* d,
                                        const uint32_t* a,
                                        const uint32_t* b) {
    asm volatile(
        "mma.sync.aligned.m16n8k16.row.col.f32.f16.f16.f32 "
        "{%0,%1,%2,%3}, {%4,%5,%6,%7}, {%8,%9}, {%0,%1,%2,%3};\n"
        : "+f"(d[0]), "+f"(d[1]), "+f"(d[2]), "+f"(d[3])
        : "r"(a[0]), "r"(a[1]), "r"(a[2]), "r"(a[3]),
          "r"(b[0]), "r"(b[1]));
}
__device__ __forceinline__ void cp16s(uint32_t saddr, const void* g) {
    asm volatile("cp.async.cg.shared.global [%0], [%1], 16;\n"
                 :: "r"(saddr), "l"(g));
}
__device__ __forceinline__ void cp_commit() {
    asm volatile("cp.async.commit_group;\n");
}
__device__ __forceinline__ void ldsm4(uint32_t* r, uint32_t saddr) {
    asm volatile("ldmatrix.sync.aligned.m8n8.x4.shared.b16 {%0,%1,%2,%3}, [%4];\n"
                 : "=r"(r[0]), "=r"(r[1]), "=r"(r[2]), "=r"(r[3]) : "r"(saddr));
}

// ---------------- convert kernels ------------------------------------------
__global__ __launch_bounds__(256)
void cvt_kernel(const float* __restrict__ x, __half* __restrict__ hi,
                int off, int n) {
    int i = off + (blockIdx.x*256 + threadIdx.x)*8;
    if (i >= off + n) return;
    float4 a = *(const float4*)(x + i);
    float4 b = *(const float4*)(x + i + 4);
    __half2* o = (__half2*)(hi + i);
    o[0] = __floats2half2_rn(a.x, a.y);
    o[1] = __floats2half2_rn(a.z, a.w);
    o[2] = __floats2half2_rn(b.x, b.y);
    o[3] = __floats2half2_rn(b.z, b.w);
}

// All four weight transposes in one launch. z: 0=Wq, 1=Wo, 2=Wk, 3=Wv.
__global__ __launch_bounds__(256)
void splitT_all_kernel(const float* __restrict__ Wq, __half* tq,
                       const float* __restrict__ Wo, __half* to,
                       const float* __restrict__ Wk, __half* tk,
                       const float* __restrict__ Wv, __half* tv) {
    int z = blockIdx.z;
    const float* W; __half* th; int K, N;
    if      (z == 0) { W = Wq; th = tq; K = D_;     N = H_*HD_; }
    else if (z == 1) { W = Wo; th = to; K = H_*HD_; N = D_;     }
    else if (z == 2) { W = Wk; th = tk; K = D_;     N = HD_;    }
    else             { W = Wv; th = tv; K = D_;     N = HD_;    }
    int n0 = blockIdx.x*32, k0 = blockIdx.y*32;
    if (n0 >= N || k0 >= K) return;
    __shared__ float tile[32][33];
    int tx = threadIdx.x & 31, ty = threadIdx.x >> 5;
    #pragma unroll
    for (int r = 0; r < 32; r += 8)
        tile[ty + r][tx] = W[(size_t)(k0 + ty + r)*N + n0 + tx];
    __syncthreads();
    #pragma unroll
    for (int r = 0; r < 32; r += 8) {
        float v = tile[tx][ty + r];
        th[(size_t)(n0 + ty + r)*K + k0 + tx] = __float2half_rn(v);
    }
}

// ============================================================================
// hgemm: single-term fp16 GEMM — R11 measured config (128x128x16, 2 CTA/SM,
// 5-stage cp.async.cg + ldmatrix, warp tile 64x32).
// ============================================================================
#define LDWW 12            // words per row (8 data + 4 pad)
#define SECW (128*LDWW)    // 1536 words per section
#define STW  (2*SECW)      // 3072 words per stage (A, B)
#define NSTG 5
#define SMEM_BYTES (NSTG*STW*4)   // 61440

__global__ __launch_bounds__(256, 2)
void hgemm_kernel(int M, int K, int nq, int nk,
                  const __half* __restrict__ Ah,
                  const __half* __restrict__ qBh, float* __restrict__ qC, int qN,
                  const __half* __restrict__ kBh, float* __restrict__ kC,
                  const __half* __restrict__ vBh, float* __restrict__ vC) {
    extern __shared__ uint32_t smem[];
    const uint32_t smem_u32 = (uint32_t)__cvta_generic_to_shared(smem);

    const int cx = blockIdx.x;
    const __half* Bh;
    float* C;
    int N, ccol;
    if (cx < nq)           { Bh = qBh; C = qC; N = qN;  ccol = cx; }
    else if (cx < nq + nk) { Bh = kBh; C = kC; N = 256; ccol = cx - nq; }
    else                   { Bh = vBh; C = vC; N = 256; ccol = cx - nq - nk; }

    const int tid = threadIdx.x, lane = tid & 31, warp = tid >> 5;
    const int warpM = warp & 1, warpN = warp >> 1;
    const int cRow = blockIdx.y;

    const int row = tid >> 1, half = tid & 1;
    const __half* aH = Ah + (size_t)(cRow*128 + row)*K + half*8;
    const __half* bH = Bh + (size_t)(ccol*128 + row)*K + half*8;
    const uint32_t dstw = row*LDWW + half*4;

    const int l7 = lane & 7;
    const uint32_t aoffw = (uint32_t)((warpM*64 + l7 + ((lane>>3)&1)*8)*LDWW + (lane>>4)*4);
    uint32_t boffw[2];
    #pragma unroll
    for (int p = 0; p < 2; p++)
        boffw[p] = (uint32_t)((warpN*32 + p*16 + l7 + ((lane>>4)&1)*8)*LDWW + ((lane>>3)&1)*4);

    float acc[4][4][4];
    #pragma unroll
    for (int mt = 0; mt < 4; mt++)
        #pragma unroll
        for (int nt = 0; nt < 4; nt++)
            #pragma unroll
            for (int i = 0; i < 4; i++) acc[mt][nt][i] = 0.f;

    const int KT = K >> 4;

    #pragma unroll
    for (int s = 0; s < NSTG - 1; s++) {
        const int ko = s*16;
        const uint32_t sb = smem_u32 + (s*STW)*4;
        cp16s(sb + dstw*4,          aH + ko);
        cp16s(sb + (SECW + dstw)*4, bH + ko);
        cp_commit();
    }

    int sc = 0;
    for (int kt = 0; kt < KT; kt++) {
        if (kt < KT - 3)      { asm volatile("cp.async.wait_group 3;\n"); }
        else if (kt < KT - 2) { asm volatile("cp.async.wait_group 2;\n"); }
        else if (kt < KT - 1) { asm volatile("cp.async.wait_group 1;\n"); }
        else                  { asm volatile("cp.async.wait_group 0;\n"); }
        __syncthreads();

        if (kt + NSTG - 1 < KT) {
            int sl = sc + (NSTG - 1); if (sl >= NSTG) sl -= NSTG;
            const int ko = (kt + NSTG - 1)*16;
            const uint32_t sb = smem_u32 + (sl*STW)*4;
            cp16s(sb + dstw*4,          aH + ko);
            cp16s(sb + (SECW + dstw)*4, bH + ko);
            cp_commit();
        }

        const uint32_t sb = smem_u32 + (sc*STW)*4;

        uint32_t bhf[2][4];
        #pragma unroll
        for (int p = 0; p < 2; p++)
            ldsm4(bhf[p], sb + (SECW + boffw[p])*4);

        #pragma unroll
        for (int mt = 0; mt < 4; mt++) {
            uint32_t ahf[4];
            ldsm4(ahf, sb + (aoffw + mt*16*LDWW)*4);
            #pragma unroll
            for (int nt = 0; nt < 4; nt++) {
                const uint32_t* bp = &bhf[nt >> 1][(nt & 1)*2];
                mma_f16(acc[mt][nt], ahf, bp);
            }
        }
        sc = (sc + 1 == NSTG) ? 0 : sc + 1;
    }

    const int g = lane >> 2, t4 = lane & 3;
    float* Cb = C + (size_t)cRow*128*N + ccol*128;
    #pragma unroll
    for (int mt = 0; mt < 4; mt++) {
        const int r0 = warpM*64 + mt*16 + g;
        #pragma unroll
        for (int nt = 0; nt < 4; nt++) {
            const int c = warpN*32 + nt*8 + t4*2;
            *(float2*)&Cb[(size_t)r0 * N + c]       = make_float2(acc[mt][nt][0], acc[mt][nt][1]);
            *(float2*)&Cb[(size_t)(r0 + 8) * N + c] = make_float2(acc[mt][nt][2], acc[mt][nt][3]);
        }
    }
}

// ============================================================================
// hedgehog2 (unchanged — measured 54us/call)
// ============================================================================
#define XS_STRIDE 260
#define FS_STRIDE 68
#define HG_SMEM ((64*XS_STRIDE + 64*FS_STRIDE + 128)*4)

__global__ __launch_bounds__(256, 2)
void hedgehog2_kernel(const float* __restrict__ x,
                      const float* __restrict__ cs,
                      const float* __restrict__ sn,
                      const float* __restrict__ fm,
                      float* __restrict__ outf,
                      int xh, float scale) {
    extern __shared__ float sm[];
    float* xs = sm;
    float* fs = sm + 64*XS_STRIDE;
    float* mz = fs + 64*FS_STRIDE;

    const int h = blockIdx.y, b = blockIdx.z;
    const int l0 = blockIdx.x * 64;
    const int t = threadIdx.x;
    const int srcH = (xh == 1) ? 0 : h;

    const float* xb = x + ((size_t)(b*L_ + l0)*xh + srcH)*HD_;
    const size_t xstride = (size_t)xh*HD_;
    #pragma unroll
    for (int p = 0; p < 16; p++) {
        int idx4 = p*256 + t;
        int r = idx4 >> 6, c4 = idx4 & 63;
        float4 v = *(const float4*)&xb[r*xstride + c4*4];
        *(float4*)&xs[r*XS_STRIDE + c4*4] = v;
    }
    __syncthreads();

    #pragma unroll
    for (int p = 0; p < 32; p++) {
        int e = p*256 + t;
        int r = e >> 7, j = e & 127;
        float c = cs[(l0 + r)*HALF_ + j];
        float s = sn[(l0 + r)*HALF_ + j];
        float x1 = xs[r*XS_STRIDE + j], x2 = xs[r*XS_STRIDE + j + 128];
        xs[r*XS_STRIDE + j]       = x1*c - x2*s;
        xs[r*XS_STRIDE + j + 128] = x1*s + x2*c;
    }
    __syncthreads();

    const int tr = t >> 4, tc = t & 15;
    float acc[4][4];
    #pragma unroll
    for (int i = 0; i < 4; i++)
        #pragma unroll
        for (int j = 0; j < 4; j++) acc[i][j] = 0.f;

    const float* fmh = fm + (size_t)h*HD_*FD_;
    for (int dt = 0; dt < 4; dt++) {
        #pragma unroll
        for (int p = 0; p < 4; p++) {
            int idx4 = p*256 + t;
            int r = idx4 >> 4, c4 = idx4 & 15;
            float4 v = *(const float4*)&fmh[(size_t)(dt*64 + r)*FD_ + c4*4];
            *(float4*)&fs[r*FS_STRIDE + c4*4] = v;
        }
        __syncthreads();

        #pragma unroll 4
        for (int dd = 0; dd < 64; dd += 4) {
            float4 xv[4], fv[4];
            #pragma unroll
            for (int i = 0; i < 4; i++)
                xv[i] = *(const float4*)&xs[(tr*4 + i)*XS_STRIDE + dt*64 + dd];
            #pragma unroll
            for (int k = 0; k < 4; k++)
                fv[k] = *(const float4*)&fs[(dd + k)*FS_STRIDE + tc*4];
            #pragma unroll
            for (int i = 0; i < 4; i++) {
                float* fvp0 = (float*)&fv[0];
                float* fvp1 = (float*)&fv[1];
                float* fvp2 = (float*)&fv[2];
                float* fvp3 = (float*)&fv[3];
                #pragma unroll
                for (int j = 0; j < 4; j++)
                    acc[i][j] += xv[i].x*fvp0[j] + xv[i].y*fvp1[j]
                               + xv[i].z*fvp2[j] + xv[i].w*fvp3[j];
            }
        }
        __syncthreads();
    }

    #pragma unroll
    for (int i = 0; i < 4; i++)
        *(float4*)&fs[(tr*4 + i)*FS_STRIDE + tc*4] =
            make_float4(acc[i][0], acc[i][1], acc[i][2], acc[i][3]);
    __syncthreads();

    const int warp = t >> 5, lane = t & 31;
    for (int rr = 0; rr < 8; rr++) {
        int rowi = warp*8 + rr;
        float v0 = fs[rowi*FS_STRIDE + lane];
        float v1 = fs[rowi*FS_STRIDE + lane + 32];
        float m = fmaxf(fabsf(v0), fabsf(v1));
        #pragma unroll
        for (int off = 16; off > 0; off >>= 1)
            m = fmaxf(m, __shfl_xor_sync(0xFFFFFFFF, m, off));
        float z = __expf(v0 - m) + __expf(-v0 - m)
                + __expf(v1 - m) + __expf(-v1 - m);
        #pragma unroll
        for (int off = 16; off > 0; off >>= 1)
            z += __shfl_xor_sync(0xFFFFFFFF, z, off);
        if (lane == 0) { mz[rowi] = m; mz[64 + rowi] = z; }
    }
    __syncthreads();

    float* ob = outf + ((size_t)(b*H_ + h)*L_ + l0)*FEAT_;
    #pragma unroll
    for (int p = 0; p < 8; p++) {
        int idx4 = p*256 + t;
        int rowi = idx4 >> 5, c4 = idx4 & 31;
        int f = c4*4;
        float m = mz[rowi], z = mz[64 + rowi];
        float inv = scale / z;
        float4 pv;
        if (f < 64) {
            pv = *(const float4*)&fs[rowi*FS_STRIDE + f];
            pv.x = __expf(pv.x - m)*inv; pv.y = __expf(pv.y - m)*inv;
            pv.z = __expf(pv.z - m)*inv; pv.w = __expf(pv.w - m)*inv;
        } else {
            pv = *(const float4*)&fs[rowi*FS_STRIDE + f - 64];
            pv.x = __expf(-pv.x - m)*inv; pv.y = __expf(-pv.y - m)*inv;
            pv.z = __expf(-pv.z - m)*inv; pv.w = __expf(-pv.w - m)*inv;
        }
        *(float4*)&ob[(size_t)rowi*FEAT_ + f] = pv;
    }
}

// ============================================================================
// kvcum: fused per-chunk kv state + EXCLUSIVE cumsum, 64f x 64d tiles.
// grid (2 ft, 4 dq, 16 bh) = 128 blocks; thread tile 4f x 4d.
// Each block walks chunks n=0..31: write exclusive prefix, accumulate chunk.
// ============================================================================
__global__ __launch_bounds__(256)
void kvcum_kernel(const float* __restrict__ kf, const float* __restrict__ v,
                  float* __restrict__ kv) {
    __shared__ float ks[32][64];    // 8 KB
    __shared__ float vs[32][64];    // 8 KB
    const int ft = blockIdx.x;      // f tile (64 wide)
    const int dq = blockIdx.y;      // d quarter (64 wide)
    const int bh = blockIdx.z;
    const int b  = bh / H_;
    const int t  = threadIdx.x;
    const int tf = t >> 4;          // 0..15 -> f rows tf*4..+3 (within 64)
    const int td = t & 15;          // 0..15 -> d cols td*4..+3

    const float* kfb = kf + ((size_t)bh*L_)*FEAT_ + ft*64;
    const float* vb  = v  + ((size_t)b*L_)*HD_ + dq*64;

    float acc[4][4];
    #pragma unroll
    for (int i = 0; i < 4; i++)
        #pragma unroll
        for (int j = 0; j < 4; j++) acc[i][j] = 0.f;

    for (int n = 0; n < NCH_; n++) {
        // write exclusive prefix for chunk n
        float* out = kv + ((size_t)(bh*NCH_ + n)*FEAT_ + ft*64)*HD_ + dq*64;
        #pragma unroll
        for (int i = 0; i < 4; i++)
            *(float4*)&out[(size_t)(tf*4 + i)*HD_ + td*4] =
                make_float4(acc[i][0], acc[i][1], acc[i][2], acc[i][3]);

        // accumulate chunk n (two 32-row halves)
        for (int cc = 0; cc < 2; cc++) {
            const int r0 = n*CHUNK_ + cc*32;
            #pragma unroll
            for (int i = 0; i < 2; i++) {
                int e = i*256 + t;
                int r = e >> 4, c4 = e & 15;
                *(float4*)&ks[r][c4*4] = *(const float4*)&kfb[(size_t)(r0 + r)*FEAT_ + c4*4];
                *(float4*)&vs[r][c4*4] = *(const float4*)&vb[(size_t)(r0 + r)*HD_ + c4*4];
            }
            __syncthreads();

            #pragma unroll 8
            for (int c = 0; c < 32; c++) {
                float4 ka = *(const float4*)&ks[c][tf*4];
                float4 va = *(const float4*)&vs[c][td*4];
                float kk[4] = {ka.x, ka.y, ka.z, ka.w};
                float vv[4] = {va.x, va.y, va.z, va.w};
                #pragma unroll
                for (int i = 0; i < 4; i++)
                    #pragma unroll
                    for (int j = 0; j < 4; j++)
                        acc[i][j] += kk[i]*vv[j];
            }
            __syncthreads();
        }
    }
}

// ---------------- inter + intra chunk attention (fp16 half2 output) -------
__global__ __launch_bounds__(256)
void attn_kernel(const float* __restrict__ qf, const float* __restrict__ kf,
                 const float* __restrict__ v,  const float* __restrict__ kv,
                 __half* __restrict__ oh) {
    __shared__ float qs[CHUNK_][FEAT_];
    __shared__ float ss[CHUNK_][CHUNK_];
    int n = blockIdx.x, h = blockIdx.y, b = blockIdx.z;
    int bh = b*H_ + h;
    int t = threadIdx.x;
    const int c2 = (t & 127) * 2;
    const int rh = t >> 7;

    const float* qp = qf + ((size_t)bh*L_ + n*CHUNK_)*FEAT_;
    for (int e = t; e < CHUNK_*FEAT_; e += 256) qs[e/FEAT_][e%FEAT_] = qp[e];
    __syncthreads();

    float acc[32][2];
    #pragma unroll
    for (int i = 0; i < 32; i++) { acc[i][0] = 0.f; acc[i][1] = 0.f; }

    const float* kvp = kv + ((size_t)(bh*NCH_ + n)*FEAT_)*HD_;
    for (int f = 0; f < FEAT_; f += 4) {
        float2 k0 = *(const float2*)&kvp[(size_t)(f+0)*HD_ + c2];
        float2 k1 = *(const float2*)&kvp[(size_t)(f+1)*HD_ + c2];
        float2 k2 = *(const float2*)&kvp[(size_t)(f+2)*HD_ + c2];
        float2 k3 = *(const float2*)&kvp[(size_t)(f+3)*HD_ + c2];
        #pragma unroll
        for (int i = 0; i < 32; i++) {
            float4 qv = *(const float4*)&qs[rh*32 + i][f];
            acc[i][0] += qv.x*k0.x + qv.y*k1.x + qv.z*k2.x + qv.w*k3.x;
            acc[i][1] += qv.x*k0.y + qv.y*k1.y + qv.z*k2.y + qv.w*k3.y;
        }
    }

    {
        const float* kp = kf + ((size_t)bh*L_ + n*CHUNK_)*FEAT_;
        int i   = t / 4;
        int jp0 = (t % 4) * 16;
        for (int jj = 0; jj < 16; jj++) {
            int jp = jp0 + jj;
            float sum = 0.f;
            if (jp <= i) {
                const float* krow = kp + (size_t)jp*FEAT_;
                #pragma unroll 8
                for (int f = 0; f < FEAT_; f += 4) {
                    float4 qv = *(const float4*)&qs[i][f];
                    float4 kr = *(const float4*)&krow[f];
                    sum += qv.x*kr.x + qv.y*kr.y + qv.z*kr.z + qv.w*kr.w;
                }
            }
            ss[i][jp] = sum;
        }
    }
    __syncthreads();

    const float* vp = v + ((size_t)b*L_ + n*CHUNK_)*HD_;
    for (int jp = 0; jp < CHUNK_; jp += 4) {
        float2 v0 = *(const float2*)&vp[(size_t)(jp+0)*HD_ + c2];
        float2 v1 = *(const float2*)&vp[(size_t)(jp+1)*HD_ + c2];
        float2 v2 = *(const float2*)&vp[(size_t)(jp+2)*HD_ + c2];
        float2 v3 = *(const float2*)&vp[(size_t)(jp+3)*HD_ + c2];
        #pragma unroll
        for (int i = 0; i < 32; i++) {
            float4 sv = *(const float4*)&ss[rh*32 + i][jp];
            acc[i][0] += sv.x*v0.x + sv.y*v1.x + sv.z*v2.x + sv.w*v3.x;
            acc[i][1] += sv.x*v0.y + sv.y*v1.y + sv.z*v2.y + sv.w*v3.y;
        }
    }

    __half* op = oh + ((size_t)(b*L_ + n*CHUNK_ + rh*32))*(H_*HD_) + h*HD_ + c2;
    #pragma unroll
    for (int i = 0; i < 32; i++)
        *(__half2*)&op[(size_t)i*(H_*HD_)] = __floats2half2_rn(acc[i][0], acc[i][1]);
}

// ---------------- launch ---------------------------------------------------
extern "C" void kernel_launch(void* const* d_in, const int* in_sizes, int n_in,
                              void* d_out, int out_size) {
    const float* hidden = (const float*)d_in[0];
    const float* fcos   = (const float*)d_in[1];
    const float* fsin   = (const float*)d_in[2];
    // d_in[3] = mask (unused)
    const float* Wq     = (const float*)d_in[4];
    const float* Wk     = (const float*)d_in[5];
    const float* Wv     = (const float*)d_in[6];
    const float* Wo     = (const float*)d_in[7];
    const float* fmq    = (const float*)d_in[8];
    const float* fmk    = (const float*)d_in[9];
    float* out          = (float*)d_out;

    float *q, *k, *v, *qf, *kf, *kv;
    cudaGetSymbolAddress((void**)&q,  g_q);
    cudaGetSymbolAddress((void**)&k,  g_k);
    cudaGetSymbolAddress((void**)&v,  g_v);
    cudaGetSymbolAddress((void**)&qf, g_qf);
    cudaGetSymbolAddress((void**)&kf, g_kf);
    cudaGetSymbolAddress((void**)&kv, g_kv);

    __half *hh,*oh,*wqh,*wkh,*wvh,*woh;
    cudaGetSymbolAddress((void**)&hh,  g_hh);
    cudaGetSymbolAddress((void**)&oh,  g_oh);
    cudaGetSymbolAddress((void**)&wqh, g_wqh);
    cudaGetSymbolAddress((void**)&wkh, g_wkh);
    cudaGetSymbolAddress((void**)&wvh, g_wvh);
    cudaGetSymbolAddress((void**)&woh, g_woh);

    cudaFuncSetAttribute(hgemm_kernel,
                         cudaFuncAttributeMaxDynamicSharedMemorySize, SMEM_BYTES);
    cudaFuncSetAttribute(hedgehog2_kernel,
                         cudaFuncAttributeMaxDynamicSharedMemorySize, HG_SMEM);

    const int M = B_*L_;   // 4096
    const float qscale = 0.08838834764831845f;   // 128^-0.5
    const int halfN = (M*D_)/2;

    // 0: all weight transposes
    splitT_all_kernel<<<dim3(64, 64, 4), 256>>>(Wq, wqh, Wo, woh, Wk, wkh, Wv, wvh);
    // 1,2: convert hidden -> fp16 (two halves)
    cvt_kernel<<<halfN/2048, 256>>>(hidden, hh, 0,     halfN);
    cvt_kernel<<<halfN/2048, 256>>>(hidden, hh, halfN, halfN);
    // 3: fused Q+K+V projections (PROFILED slot)
    hgemm_kernel<<<dim3(20, M/128), 256, SMEM_BYTES>>>(M, D_, 16, 2,
        hh, wqh, q, H_*HD_, wkh, k, wvh, v);
    // 4: hedgehog q (fused RoPE)
    hedgehog2_kernel<<<dim3(L_/64, H_, B_), 256, HG_SMEM>>>(q, fcos, fsin, fmq, qf, H_, qscale);
    // 5: hedgehog k
    hedgehog2_kernel<<<dim3(L_/64, H_, B_), 256, HG_SMEM>>>(k, fcos, fsin, fmk, kf, 1, 1.0f);
    // 6: fused kv states + exclusive cumsum (128 blocks)
    kvcum_kernel<<<dim3(2, 4, B_*H_), 256>>>(kf, v, kv);
    // 7: inter + intra attention -> fp16 oh
    attn_kernel<<<dim3(NCH_, H_, B_), 256>>>(qf, kf, v, kv, oh);
    // 8: output projection
    hgemm_kernel<<<dim3(16, M/128), 256, SMEM_BYTES>>>(M, H_*HD_, 16, 0,
        oh, woh, out, D_, woh, out, woh, out);
}

// round 14
// speedup vs baseline: 1.2723x; 1.0317x over previous
#include <cuda_runtime.h>
#include <cuda_fp16.h>
#include <math.h>
#include <stdint.h>

// Problem constants
#define B_ 2
#define L_ 2048
#define D_ 2048
#define H_ 8
#define HD_ 256
#define FD_ 64
#define FEAT_ 128          // 2*FD
#define CHUNK_ 64
#define NCH_ (L_/CHUNK_)   // 32
#define HALF_ (HD_/2)      // 128

// ---------------- scratch (device globals; no allocation allowed) ----------
__device__ float g_q [B_*L_*H_*HD_];
__device__ float g_k [B_*L_*HD_];
__device__ float g_v [B_*L_*HD_];
__device__ float g_qf[B_*H_*L_*FEAT_];
__device__ float g_kf[B_*H_*L_*FEAT_];
__device__ float g_kv[B_*H_*NCH_*FEAT_*HD_];

__device__ __half g_hh[B_*L_*D_];
__device__ __half g_oh[B_*L_*H_*HD_];
__device__ __half g_wqh[D_*H_*HD_];
__device__ __half g_wkh[HD_*D_];
__device__ __half g_wvh[HD_*D_];
__device__ __half g_woh[D_*H_*HD_];

// ---------------- helpers ---------------------------------------------------
__device__ __forceinline__ void mma_f16(float* d,
                                        const uint32_t* a,
                                        const uint32_t* b) {
    asm volatile(
        "mma.sync.aligned.m16n8k16.row.col.f32.f16.f16.f32 "
        "{%0,%1,%2,%3}, {%4,%5,%6,%7}, {%8,%9}, {%0,%1,%2,%3};\n"
        : "+f"(d[0]), "+f"(d[1]), "+f"(d[2]), "+f"(d[3])
        : "r"(a[0]), "r"(a[1]), "r"(a[2]), "r"(a[3]),
          "r"(b[0]), "r"(b[1]));
}
__device__ __forceinline__ void cp16s(uint32_t saddr, const void* g) {
    asm volatile("cp.async.cg.shared.global [%0], [%1], 16;\n"
                 :: "r"(saddr), "l"(g));
}
__device__ __forceinline__ void cp_commit() {
    asm volatile("cp.async.commit_group;\n");
}
__device__ __forceinline__ void ldsm4(uint32_t* r, uint32_t saddr) {
    asm volatile("ldmatrix.sync.aligned.m8n8.x4.shared.b16 {%0,%1,%2,%3}, [%4];\n"
                 : "=r"(r[0]), "=r"(r[1]), "=r"(r[2]), "=r"(r[3]) : "r"(saddr));
}

// ---------------- convert kernels ------------------------------------------
__global__ __launch_bounds__(256)
void cvt_kernel(const float* __restrict__ x, __half* __restrict__ hi,
                int off, int n) {
    int i = off + (blockIdx.x*256 + threadIdx.x)*8;
    if (i >= off + n) return;
    float4 a = *(const float4*)(x + i);
    float4 b = *(const float4*)(x + i + 4);
    __half2* o = (__half2*)(hi + i);
    o[0] = __floats2half2_rn(a.x, a.y);
    o[1] = __floats2half2_rn(a.z, a.w);
    o[2] = __floats2half2_rn(b.x, b.y);
    o[3] = __floats2half2_rn(b.z, b.w);
}

// All four weight transposes in one launch. z: 0=Wq, 1=Wo, 2=Wk, 3=Wv.
__global__ __launch_bounds__(256)
void splitT_all_kernel(const float* __restrict__ Wq, __half* tq,
                       const float* __restrict__ Wo, __half* to,
                       const float* __restrict__ Wk, __half* tk,
                       const float* __restrict__ Wv, __half* tv) {
    int z = blockIdx.z;
    const float* W; __half* th; int K, N;
    if      (z == 0) { W = Wq; th = tq; K = D_;     N = H_*HD_; }
    else if (z == 1) { W = Wo; th = to; K = H_*HD_; N = D_;     }
    else if (z == 2) { W = Wk; th = tk; K = D_;     N = HD_;    }
    else             { W = Wv; th = tv; K = D_;     N = HD_;    }
    int n0 = blockIdx.x*32, k0 = blockIdx.y*32;
    if (n0 >= N || k0 >= K) return;
    __shared__ float tile[32][33];
    int tx = threadIdx.x & 31, ty = threadIdx.x >> 5;
    #pragma unroll
    for (int r = 0; r < 32; r += 8)
        tile[ty + r][tx] = W[(size_t)(k0 + ty + r)*N + n0 + tx];
    __syncthreads();
    #pragma unroll
    for (int r = 0; r < 32; r += 8) {
        float v = tile[tx][ty + r];
        th[(size_t)(n0 + ty + r)*K + k0 + tx] = __float2half_rn(v);
    }
}

// ============================================================================
// hgemm: single-term fp16 GEMM — R11 measured config (128x128x16, 2 CTA/SM,
// 5-stage cp.async.cg + ldmatrix, warp tile 64x32). DO NOT TOUCH.
// ============================================================================
#define LDWW 12            // words per row (8 data + 4 pad)
#define SECW (128*LDWW)    // 1536 words per section
#define STW  (2*SECW)      // 3072 words per stage (A, B)
#define NSTG 5
#define SMEM_BYTES (NSTG*STW*4)   // 61440

__global__ __launch_bounds__(256, 2)
void hgemm_kernel(int M, int K, int nq, int nk,
                  const __half* __restrict__ Ah,
                  const __half* __restrict__ qBh, float* __restrict__ qC, int qN,
                  const __half* __restrict__ kBh, float* __restrict__ kC,
                  const __half* __restrict__ vBh, float* __restrict__ vC) {
    extern __shared__ uint32_t smem[];
    const uint32_t smem_u32 = (uint32_t)__cvta_generic_to_shared(smem);

    const int cx = blockIdx.x;
    const __half* Bh;
    float* C;
    int N, ccol;
    if (cx < nq)           { Bh = qBh; C = qC; N = qN;  ccol = cx; }
    else if (cx < nq + nk) { Bh = kBh; C = kC; N = 256; ccol = cx - nq; }
    else                   { Bh = vBh; C = vC; N = 256; ccol = cx - nq - nk; }

    const int tid = threadIdx.x, lane = tid & 31, warp = tid >> 5;
    const int warpM = warp & 1, warpN = warp >> 1;
    const int cRow = blockIdx.y;

    const int row = tid >> 1, half = tid & 1;
    const __half* aH = Ah + (size_t)(cRow*128 + row)*K + half*8;
    const __half* bH = Bh + (size_t)(ccol*128 + row)*K + half*8;
    const uint32_t dstw = row*LDWW + half*4;

    const int l7 = lane & 7;
    const uint32_t aoffw = (uint32_t)((warpM*64 + l7 + ((lane>>3)&1)*8)*LDWW + (lane>>4)*4);
    uint32_t boffw[2];
    #pragma unroll
    for (int p = 0; p < 2; p++)
        boffw[p] = (uint32_t)((warpN*32 + p*16 + l7 + ((lane>>4)&1)*8)*LDWW + ((lane>>3)&1)*4);

    float acc[4][4][4];
    #pragma unroll
    for (int mt = 0; mt < 4; mt++)
        #pragma unroll
        for (int nt = 0; nt < 4; nt++)
            #pragma unroll
            for (int i = 0; i < 4; i++) acc[mt][nt][i] = 0.f;

    const int KT = K >> 4;

    #pragma unroll
    for (int s = 0; s < NSTG - 1; s++) {
        const int ko = s*16;
        const uint32_t sb = smem_u32 + (s*STW)*4;
        cp16s(sb + dstw*4,          aH + ko);
        cp16s(sb + (SECW + dstw)*4, bH + ko);
        cp_commit();
    }

    int sc = 0;
    for (int kt = 0; kt < KT; kt++) {
        if (kt < KT - 3)      { asm volatile("cp.async.wait_group 3;\n"); }
        else if (kt < KT - 2) { asm volatile("cp.async.wait_group 2;\n"); }
        else if (kt < KT - 1) { asm volatile("cp.async.wait_group 1;\n"); }
        else                  { asm volatile("cp.async.wait_group 0;\n"); }
        __syncthreads();

        if (kt + NSTG - 1 < KT) {
            int sl = sc + (NSTG - 1); if (sl >= NSTG) sl -= NSTG;
            const int ko = (kt + NSTG - 1)*16;
            const uint32_t sb = smem_u32 + (sl*STW)*4;
            cp16s(sb + dstw*4,          aH + ko);
            cp16s(sb + (SECW + dstw)*4, bH + ko);
            cp_commit();
        }

        const uint32_t sb = smem_u32 + (sc*STW)*4;

        uint32_t bhf[2][4];
        #pragma unroll
        for (int p = 0; p < 2; p++)
            ldsm4(bhf[p], sb + (SECW + boffw[p])*4);

        #pragma unroll
        for (int mt = 0; mt < 4; mt++) {
            uint32_t ahf[4];
            ldsm4(ahf, sb + (aoffw + mt*16*LDWW)*4);
            #pragma unroll
            for (int nt = 0; nt < 4; nt++) {
                const uint32_t* bp = &bhf[nt >> 1][(nt & 1)*2];
                mma_f16(acc[mt][nt], ahf, bp);
            }
        }
        sc = (sc + 1 == NSTG) ? 0 : sc + 1;
    }

    const int g = lane >> 2, t4 = lane & 3;
    float* Cb = C + (size_t)cRow*128*N + ccol*128;
    #pragma unroll
    for (int mt = 0; mt < 4; mt++) {
        const int r0 = warpM*64 + mt*16 + g;
        #pragma unroll
        for (int nt = 0; nt < 4; nt++) {
            const int c = warpN*32 + nt*8 + t4*2;
            *(float2*)&Cb[(size_t)r0 * N + c]       = make_float2(acc[mt][nt][0], acc[mt][nt][1]);
            *(float2*)&Cb[(size_t)(r0 + 8) * N + c] = make_float2(acc[mt][nt][2], acc[mt][nt][3]);
        }
    }
}

// ============================================================================
// hedgehog2 merged q+k: blockIdx.z selects (b, which). which=0 -> q path,
// which=1 -> k path. Same body as the measured 54us kernel.
// ============================================================================
#define XS_STRIDE 260
#define FS_STRIDE 68
#define HG_SMEM ((64*XS_STRIDE + 64*FS_STRIDE + 128)*4)

__global__ __launch_bounds__(256, 2)
void hedgehog2_kernel(const float* __restrict__ xq,
                      const float* __restrict__ xk,
                      const float* __restrict__ cs,
                      const float* __restrict__ sn,
                      const float* __restrict__ fmq,
                      const float* __restrict__ fmk,
                      float* __restrict__ qf,
                      float* __restrict__ kf,
                      float qscale) {
    extern __shared__ float sm[];
    float* xs = sm;
    float* fs = sm + 64*XS_STRIDE;
    float* mz = fs + 64*FS_STRIDE;

    const int h = blockIdx.y;
    const int which = blockIdx.z & 1;
    const int b = blockIdx.z >> 1;
    const int l0 = blockIdx.x * 64;
    const int t = threadIdx.x;

    const float* x   = which ? xk  : xq;
    const float* fm  = which ? fmk : fmq;
    float* outf      = which ? kf  : qf;
    const int xh     = which ? 1   : H_;
    const float scale = which ? 1.0f : qscale;
    const int srcH = (xh == 1) ? 0 : h;

    const float* xb = x + ((size_t)(b*L_ + l0)*xh + srcH)*HD_;
    const size_t xstride = (size_t)xh*HD_;
    #pragma unroll
    for (int p = 0; p < 16; p++) {
        int idx4 = p*256 + t;
        int r = idx4 >> 6, c4 = idx4 & 63;
        float4 v = *(const float4*)&xb[r*xstride + c4*4];
        *(float4*)&xs[r*XS_STRIDE + c4*4] = v;
    }
    __syncthreads();

    #pragma unroll
    for (int p = 0; p < 32; p++) {
        int e = p*256 + t;
        int r = e >> 7, j = e & 127;
        float c = cs[(l0 + r)*HALF_ + j];
        float s = sn[(l0 + r)*HALF_ + j];
        float x1 = xs[r*XS_STRIDE + j], x2 = xs[r*XS_STRIDE + j + 128];
        xs[r*XS_STRIDE + j]       = x1*c - x2*s;
        xs[r*XS_STRIDE + j + 128] = x1*s + x2*c;
    }
    __syncthreads();

    const int tr = t >> 4, tc = t & 15;
    float acc[4][4];
    #pragma unroll
    for (int i = 0; i < 4; i++)
        #pragma unroll
        for (int j = 0; j < 4; j++) acc[i][j] = 0.f;

    const float* fmh = fm + (size_t)h*HD_*FD_;
    for (int dt = 0; dt < 4; dt++) {
        #pragma unroll
        for (int p = 0; p < 4; p++) {
            int idx4 = p*256 + t;
            int r = idx4 >> 4, c4 = idx4 & 15;
            float4 v = *(const float4*)&fmh[(size_t)(dt*64 + r)*FD_ + c4*4];
            *(float4*)&fs[r*FS_STRIDE + c4*4] = v;
        }
        __syncthreads();

        #pragma unroll 4
        for (int dd = 0; dd < 64; dd += 4) {
            float4 xv[4], fv[4];
            #pragma unroll
            for (int i = 0; i < 4; i++)
                xv[i] = *(const float4*)&xs[(tr*4 + i)*XS_STRIDE + dt*64 + dd];
            #pragma unroll
            for (int k = 0; k < 4; k++)
                fv[k] = *(const float4*)&fs[(dd + k)*FS_STRIDE + tc*4];
            #pragma unroll
            for (int i = 0; i < 4; i++) {
                float* fvp0 = (float*)&fv[0];
                float* fvp1 = (float*)&fv[1];
                float* fvp2 = (float*)&fv[2];
                float* fvp3 = (float*)&fv[3];
                #pragma unroll
                for (int j = 0; j < 4; j++)
                    acc[i][j] += xv[i].x*fvp0[j] + xv[i].y*fvp1[j]
                               + xv[i].z*fvp2[j] + xv[i].w*fvp3[j];
            }
        }
        __syncthreads();
    }

    #pragma unroll
    for (int i = 0; i < 4; i++)
        *(float4*)&fs[(tr*4 + i)*FS_STRIDE + tc*4] =
            make_float4(acc[i][0], acc[i][1], acc[i][2], acc[i][3]);
    __syncthreads();

    const int warp = t >> 5, lane = t & 31;
    for (int rr = 0; rr < 8; rr++) {
        int rowi = warp*8 + rr;
        float v0 = fs[rowi*FS_STRIDE + lane];
        float v1 = fs[rowi*FS_STRIDE + lane + 32];
        float m = fmaxf(fabsf(v0), fabsf(v1));
        #pragma unroll
        for (int off = 16; off > 0; off >>= 1)
            m = fmaxf(m, __shfl_xor_sync(0xFFFFFFFF, m, off));
        float z = __expf(v0 - m) + __expf(-v0 - m)
                + __expf(v1 - m) + __expf(-v1 - m);
        #pragma unroll
        for (int off = 16; off > 0; off >>= 1)
            z += __shfl_xor_sync(0xFFFFFFFF, z, off);
        if (lane == 0) { mz[rowi] = m; mz[64 + rowi] = z; }
    }
    __syncthreads();

    float* ob = outf + ((size_t)(b*H_ + h)*L_ + l0)*FEAT_;
    #pragma unroll
    for (int p = 0; p < 8; p++) {
        int idx4 = p*256 + t;
        int rowi = idx4 >> 5, c4 = idx4 & 31;
        int f = c4*4;
        float m = mz[rowi], z = mz[64 + rowi];
        float inv = scale / z;
        float4 pv;
        if (f < 64) {
            pv = *(const float4*)&fs[rowi*FS_STRIDE + f];
            pv.x = __expf(pv.x - m)*inv; pv.y = __expf(pv.y - m)*inv;
            pv.z = __expf(pv.z - m)*inv; pv.w = __expf(pv.w - m)*inv;
        } else {
            pv = *(const float4*)&fs[rowi*FS_STRIDE + f - 64];
            pv.x = __expf(-pv.x - m)*inv; pv.y = __expf(-pv.y - m)*inv;
            pv.z = __expf(-pv.z - m)*inv; pv.w = __expf(-pv.w - m)*inv;
        }
        *(float4*)&ob[(size_t)rowi*FEAT_ + f] = pv;
    }
}

// ---------------- per-chunk kv state (register-tiled, R11 measured) --------
__global__ __launch_bounds__(256)
void kv2_kernel(const float* __restrict__ kf, const float* __restrict__ v,
                float* __restrict__ kv) {
    __shared__ float ks[32][FEAT_];
    __shared__ float vs[32][128];
    int n  = blockIdx.x;
    int dh = blockIdx.y;
    int bh = blockIdx.z;
    int b  = bh / H_;
    int t  = threadIdx.x;
    int tf = t >> 4;
    int td = t & 15;

    const float* kfp = kf + ((size_t)bh*L_ + n*CHUNK_)*FEAT_;
    const float* vp  = v  + ((size_t)b*L_  + n*CHUNK_)*HD_ + dh*128;

    float acc[8][8];
    #pragma unroll
    for (int i = 0; i < 8; i++)
        #pragma unroll
        for (int j = 0; j < 8; j++) acc[i][j] = 0.f;

    for (int cc = 0; cc < 2; cc++) {
        for (int e = t; e < 32*FEAT_; e += 256)
            ks[e >> 7][e & 127] = kfp[cc*32*FEAT_ + e];
        for (int e = t; e < 32*128; e += 256) {
            int r = e >> 7, c = e & 127;
            vs[r][c] = vp[(size_t)(cc*32 + r)*HD_ + c];
        }
        __syncthreads();

        #pragma unroll 4
        for (int c = 0; c < 32; c++) {
            float4 ka = *(const float4*)&ks[c][tf*8];
            float4 kb = *(const float4*)&ks[c][tf*8 + 4];
            float4 va = *(const float4*)&vs[c][td*4];
            float4 vb = *(const float4*)&vs[c][64 + td*4];
            float kk[8] = {ka.x,ka.y,ka.z,ka.w,kb.x,kb.y,kb.z,kb.w};
            float vv[8] = {va.x,va.y,va.z,va.w,vb.x,vb.y,vb.z,vb.w};
            #pragma unroll
            for (int i = 0; i < 8; i++)
                #pragma unroll
                for (int j = 0; j < 8; j++)
                    acc[i][j] += kk[i]*vv[j];
        }
        __syncthreads();
    }

    float* out = kv + ((size_t)(bh*NCH_ + n)*FEAT_)*HD_ + dh*128;
    #pragma unroll
    for (int i = 0; i < 8; i++) {
        size_t ro = (size_t)(tf*8 + i)*HD_;
        *(float4*)&out[ro + td*4]      = make_float4(acc[i][0], acc[i][1], acc[i][2], acc[i][3]);
        *(float4*)&out[ro + 64 + td*4] = make_float4(acc[i][4], acc[i][5], acc[i][6], acc[i][7]);
    }
}

// ---------------- exclusive cumsum, MLP-32 version (load-all-then-store) ---
__global__ void cumsum_kernel(float* __restrict__ kv) {
    int bh = blockIdx.y;
    int e  = blockIdx.x*256 + threadIdx.x;
    float* base = kv + (size_t)bh*NCH_*FEAT_*HD_ + e;

    float vals[NCH_];
    #pragma unroll
    for (int n = 0; n < NCH_; n++)
        vals[n] = base[(size_t)n*FEAT_*HD_];   // 32 independent loads (MLP=32)

    float run = 0.f;
    #pragma unroll
    for (int n = 0; n < NCH_; n++) {
        base[(size_t)n*FEAT_*HD_] = run;
        run += vals[n];
    }
}

// ---------------- inter + intra chunk attention (fp16 half2 output) -------
__global__ __launch_bounds__(256)
void attn_kernel(const float* __restrict__ qf, const float* __restrict__ kf,
                 const float* __restrict__ v,  const float* __restrict__ kv,
                 __half* __restrict__ oh) {
    __shared__ float qs[CHUNK_][FEAT_];
    __shared__ float ss[CHUNK_][CHUNK_];
    int n = blockIdx.x, h = blockIdx.y, b = blockIdx.z;
    int bh = b*H_ + h;
    int t = threadIdx.x;
    const int c2 = (t & 127) * 2;
    const int rh = t >> 7;

    const float* qp = qf + ((size_t)bh*L_ + n*CHUNK_)*FEAT_;
    for (int e = t; e < CHUNK_*FEAT_; e += 256) qs[e/FEAT_][e%FEAT_] = qp[e];
    __syncthreads();

    float acc[32][2];
    #pragma unroll
    for (int i = 0; i < 32; i++) { acc[i][0] = 0.f; acc[i][1] = 0.f; }

    const float* kvp = kv + ((size_t)(bh*NCH_ + n)*FEAT_)*HD_;
    for (int f = 0; f < FEAT_; f += 4) {
        float2 k0 = *(const float2*)&kvp[(size_t)(f+0)*HD_ + c2];
        float2 k1 = *(const float2*)&kvp[(size_t)(f+1)*HD_ + c2];
        float2 k2 = *(const float2*)&kvp[(size_t)(f+2)*HD_ + c2];
        float2 k3 = *(const float2*)&kvp[(size_t)(f+3)*HD_ + c2];
        #pragma unroll
        for (int i = 0; i < 32; i++) {
            float4 qv = *(const float4*)&qs[rh*32 + i][f];
            acc[i][0] += qv.x*k0.x + qv.y*k1.x + qv.z*k2.x + qv.w*k3.x;
            acc[i][1] += qv.x*k0.y + qv.y*k1.y + qv.z*k2.y + qv.w*k3.y;
        }
    }

    {
        const float* kp = kf + ((size_t)bh*L_ + n*CHUNK_)*FEAT_;
        int i   = t / 4;
        int jp0 = (t % 4) * 16;
        for (int jj = 0; jj < 16; jj++) {
            int jp = jp0 + jj;
            float sum = 0.f;
            if (jp <= i) {
                const float* krow = kp + (size_t)jp*FEAT_;
                #pragma unroll 8
                for (int f = 0; f < FEAT_; f += 4) {
                    float4 qv = *(const float4*)&qs[i][f];
                    float4 kr = *(const float4*)&krow[f];
                    sum += qv.x*kr.x + qv.y*kr.y + qv.z*kr.z + qv.w*kr.w;
                }
            }
            ss[i][jp] = sum;
        }
    }
    __syncthreads();

    const float* vp = v + ((size_t)b*L_ + n*CHUNK_)*HD_;
    for (int jp = 0; jp < CHUNK_; jp += 4) {
        float2 v0 = *(const float2*)&vp[(size_t)(jp+0)*HD_ + c2];
        float2 v1 = *(const float2*)&vp[(size_t)(jp+1)*HD_ + c2];
        float2 v2 = *(const float2*)&vp[(size_t)(jp+2)*HD_ + c2];
        float2 v3 = *(const float2*)&vp[(size_t)(jp+3)*HD_ + c2];
        #pragma unroll
        for (int i = 0; i < 32; i++) {
            float4 sv = *(const float4*)&ss[rh*32 + i][jp];
            acc[i][0] += sv.x*v0.x + sv.y*v1.x + sv.z*v2.x + sv.w*v3.x;
            acc[i][1] += sv.x*v0.y + sv.y*v1.y + sv.z*v2.y + sv.w*v3.y;
        }
    }

    __half* op = oh + ((size_t)(b*L_ + n*CHUNK_ + rh*32))*(H_*HD_) + h*HD_ + c2;
    #pragma unroll
    for (int i = 0; i < 32; i++)
        *(__half2*)&op[(size_t)i*(H_*HD_)] = __floats2half2_rn(acc[i][0], acc[i][1]);
}

// ---------------- launch ---------------------------------------------------
extern "C" void kernel_launch(void* const* d_in, const int* in_sizes, int n_in,
                              void* d_out, int out_size) {
    const float* hidden = (const float*)d_in[0];
    const float* fcos   = (const float*)d_in[1];
    const float* fsin   = (const float*)d_in[2];
    // d_in[3] = mask (unused)
    const float* Wq     = (const float*)d_in[4];
    const float* Wk     = (const float*)d_in[5];
    const float* Wv     = (const float*)d_in[6];
    const float* Wo     = (const float*)d_in[7];
    const float* fmq    = (const float*)d_in[8];
    const float* fmk    = (const float*)d_in[9];
    float* out          = (float*)d_out;

    float *q, *k, *v, *qf, *kf, *kv;
    cudaGetSymbolAddress((void**)&q,  g_q);
    cudaGetSymbolAddress((void**)&k,  g_k);
    cudaGetSymbolAddress((void**)&v,  g_v);
    cudaGetSymbolAddress((void**)&qf, g_qf);
    cudaGetSymbolAddress((void**)&kf, g_kf);
    cudaGetSymbolAddress((void**)&kv, g_kv);

    __half *hh,*oh,*wqh,*wkh,*wvh,*woh;
    cudaGetSymbolAddress((void**)&hh,  g_hh);
    cudaGetSymbolAddress((void**)&oh,  g_oh);
    cudaGetSymbolAddress((void**)&wqh, g_wqh);
    cudaGetSymbolAddress((void**)&wkh, g_wkh);
    cudaGetSymbolAddress((void**)&wvh, g_wvh);
    cudaGetSymbolAddress((void**)&woh, g_woh);

    cudaFuncSetAttribute(hgemm_kernel,
                         cudaFuncAttributeMaxDynamicSharedMemorySize, SMEM_BYTES);
    cudaFuncSetAttribute(hedgehog2_kernel,
                         cudaFuncAttributeMaxDynamicSharedMemorySize, HG_SMEM);

    const int M = B_*L_;   // 4096
    const float qscale = 0.08838834764831845f;   // 128^-0.5
    const int halfN = (M*D_)/2;

    // 0: all weight transposes
    splitT_all_kernel<<<dim3(64, 64, 4), 256>>>(Wq, wqh, Wo, woh, Wk, wkh, Wv, wvh);
    // 1,2: convert hidden -> fp16 (two halves)
    cvt_kernel<<<halfN/2048, 256>>>(hidden, hh, 0,     halfN);
    cvt_kernel<<<halfN/2048, 256>>>(hidden, hh, halfN, halfN);
    // 3: fused Q+K+V projections (PROFILED slot)
    hgemm_kernel<<<dim3(20, M/128), 256, SMEM_BYTES>>>(M, D_, 16, 2,
        hh, wqh, q, H_*HD_, wkh, k, wvh, v);
    // 4: hedgehog q+k merged (fused RoPE)
    hedgehog2_kernel<<<dim3(L_/64, H_, B_*2), 256, HG_SMEM>>>(
        q, k, fcos, fsin, fmq, fmk, qf, kf, qscale);
    // 5: per-chunk kv states
    kv2_kernel<<<dim3(NCH_, 2, B_*H_), 256>>>(kf, v, kv);
    // 6: exclusive cumsum (MLP-32)
    cumsum_kernel<<<dim3(128, B_*H_), 256>>>(kv);
    // 7: inter + intra attention -> fp16 oh
    attn_kernel<<<dim3(NCH_, H_, B_), 256>>>(qf, kf, v, kv, oh);
    // 8: output projection
    hgemm_kernel<<<dim3(16, M/128), 256, SMEM_BYTES>>>(M, H_*HD_, 16, 0,
        oh, woh, out, D_, woh, out, woh, out);
}

// round 15
// speedup vs baseline: 1.2929x; 1.0163x over previous
#include <cuda_runtime.h>
#include <cuda_fp16.h>
#include <math.h>
#include <stdint.h>

// Problem constants
#define B_ 2
#define L_ 2048
#define D_ 2048
#define H_ 8
#define HD_ 256
#define FD_ 64
#define FEAT_ 128          // 2*FD
#define CHUNK_ 64
#define NCH_ (L_/CHUNK_)   // 32
#define HALF_ (HD_/2)      // 128

// ---------------- scratch (device globals; no allocation allowed) ----------
__device__ float g_q [B_*L_*H_*HD_];
__device__ float g_k [B_*L_*HD_];
__device__ float g_v [B_*L_*HD_];
__device__ float g_qf[B_*H_*L_*FEAT_];
__device__ float g_kf[B_*H_*L_*FEAT_];
__device__ float g_kv[B_*H_*NCH_*FEAT_*HD_];          // per-chunk states (fp32)
__device__ __half g_kvh[B_*H_*NCH_*FEAT_*HD_];        // exclusive prefix (fp16)

__device__ __half g_hh[B_*L_*D_];
__device__ __half g_oh[B_*L_*H_*HD_];
__device__ __half g_wqh[D_*H_*HD_];
__device__ __half g_wkh[HD_*D_];
__device__ __half g_wvh[HD_*D_];
__device__ __half g_woh[D_*H_*HD_];

// ---------------- helpers ---------------------------------------------------
__device__ __forceinline__ void mma_f16(float* d,
                                        const uint32_t* a,
                                        const uint32_t* b) {
    asm volatile(
        "mma.sync.aligned.m16n8k16.row.col.f32.f16.f16.f32 "
        "{%0,%1,%2,%3}, {%4,%5,%6,%7}, {%8,%9}, {%0,%1,%2,%3};\n"
        : "+f"(d[0]), "+f"(d[1]), "+f"(d[2]), "+f"(d[3])
        : "r"(a[0]), "r"(a[1]), "r"(a[2]), "r"(a[3]),
          "r"(b[0]), "r"(b[1]));
}
__device__ __forceinline__ void cp16s(uint32_t saddr, const void* g) {
    asm volatile("cp.async.cg.shared.global [%0], [%1], 16;\n"
                 :: "r"(saddr), "l"(g));
}
__device__ __forceinline__ void cp_commit() {
    asm volatile("cp.async.commit_group;\n");
}
__device__ __forceinline__ void ldsm4(uint32_t* r, uint32_t saddr) {
    asm volatile("ldmatrix.sync.aligned.m8n8.x4.shared.b16 {%0,%1,%2,%3}, [%4];\n"
                 : "=r"(r[0]), "=r"(r[1]), "=r"(r[2]), "=r"(r[3]) : "r"(saddr));
}

// ---------------- convert kernels ------------------------------------------
__global__ __launch_bounds__(256)
void cvt_kernel(const float* __restrict__ x, __half* __restrict__ hi,
                int off, int n) {
    int i = off + (blockIdx.x*256 + threadIdx.x)*8;
    if (i >= off + n) return;
    float4 a = *(const float4*)(x + i);
    float4 b = *(const float4*)(x + i + 4);
    __half2* o = (__half2*)(hi + i);
    o[0] = __floats2half2_rn(a.x, a.y);
    o[1] = __floats2half2_rn(a.z, a.w);
    o[2] = __floats2half2_rn(b.x, b.y);
    o[3] = __floats2half2_rn(b.z, b.w);
}

// All four weight transposes in one launch. z: 0=Wq, 1=Wo, 2=Wk, 3=Wv.
__global__ __launch_bounds__(256)
void splitT_all_kernel(const float* __restrict__ Wq, __half* tq,
                       const float* __restrict__ Wo, __half* to,
                       const float* __restrict__ Wk, __half* tk,
                       const float* __restrict__ Wv, __half* tv) {
    int z = blockIdx.z;
    const float* W; __half* th; int K, N;
    if      (z == 0) { W = Wq; th = tq; K = D_;     N = H_*HD_; }
    else if (z == 1) { W = Wo; th = to; K = H_*HD_; N = D_;     }
    else if (z == 2) { W = Wk; th = tk; K = D_;     N = HD_;    }
    else             { W = Wv; th = tv; K = D_;     N = HD_;    }
    int n0 = blockIdx.x*32, k0 = blockIdx.y*32;
    if (n0 >= N || k0 >= K) return;
    __shared__ float tile[32][33];
    int tx = threadIdx.x & 31, ty = threadIdx.x >> 5;
    #pragma unroll
    for (int r = 0; r < 32; r += 8)
        tile[ty + r][tx] = W[(size_t)(k0 + ty + r)*N + n0 + tx];
    __syncthreads();
    #pragma unroll
    for (int r = 0; r < 32; r += 8) {
        float v = tile[tx][ty + r];
        th[(size_t)(n0 + ty + r)*K + k0 + tx] = __float2half_rn(v);
    }
}

// ============================================================================
// hgemm: single-term fp16 GEMM — R11 measured config (128x128x16, 2 CTA/SM,
// 5-stage cp.async.cg + ldmatrix, warp tile 64x32). DO NOT TOUCH.
// ============================================================================
#define LDWW 12            // words per row (8 data + 4 pad)
#define SECW (128*LDWW)    // 1536 words per section
#define STW  (2*SECW)      // 3072 words per stage (A, B)
#define NSTG 5
#define SMEM_BYTES (NSTG*STW*4)   // 61440

__global__ __launch_bounds__(256, 2)
void hgemm_kernel(int M, int K, int nq, int nk,
                  const __half* __restrict__ Ah,
                  const __half* __restrict__ qBh, float* __restrict__ qC, int qN,
                  const __half* __restrict__ kBh, float* __restrict__ kC,
                  const __half* __restrict__ vBh, float* __restrict__ vC) {
    extern __shared__ uint32_t smem[];
    const uint32_t smem_u32 = (uint32_t)__cvta_generic_to_shared(smem);

    const int cx = blockIdx.x;
    const __half* Bh;
    float* C;
    int N, ccol;
    if (cx < nq)           { Bh = qBh; C = qC; N = qN;  ccol = cx; }
    else if (cx < nq + nk) { Bh = kBh; C = kC; N = 256; ccol = cx - nq; }
    else                   { Bh = vBh; C = vC; N = 256; ccol = cx - nq - nk; }

    const int tid = threadIdx.x, lane = tid & 31, warp = tid >> 5;
    const int warpM = warp & 1, warpN = warp >> 1;
    const int cRow = blockIdx.y;

    const int row = tid >> 1, half = tid & 1;
    const __half* aH = Ah + (size_t)(cRow*128 + row)*K + half*8;
    const __half* bH = Bh + (size_t)(ccol*128 + row)*K + half*8;
    const uint32_t dstw = row*LDWW + half*4;

    const int l7 = lane & 7;
    const uint32_t aoffw = (uint32_t)((warpM*64 + l7 + ((lane>>3)&1)*8)*LDWW + (lane>>4)*4);
    uint32_t boffw[2];
    #pragma unroll
    for (int p = 0; p < 2; p++)
        boffw[p] = (uint32_t)((warpN*32 + p*16 + l7 + ((lane>>4)&1)*8)*LDWW + ((lane>>3)&1)*4);

    float acc[4][4][4];
    #pragma unroll
    for (int mt = 0; mt < 4; mt++)
        #pragma unroll
        for (int nt = 0; nt < 4; nt++)
            #pragma unroll
            for (int i = 0; i < 4; i++) acc[mt][nt][i] = 0.f;

    const int KT = K >> 4;

    #pragma unroll
    for (int s = 0; s < NSTG - 1; s++) {
        const int ko = s*16;
        const uint32_t sb = smem_u32 + (s*STW)*4;
        cp16s(sb + dstw*4,          aH + ko);
        cp16s(sb + (SECW + dstw)*4, bH + ko);
        cp_commit();
    }

    int sc = 0;
    for (int kt = 0; kt < KT; kt++) {
        if (kt < KT - 3)      { asm volatile("cp.async.wait_group 3;\n"); }
        else if (kt < KT - 2) { asm volatile("cp.async.wait_group 2;\n"); }
        else if (kt < KT - 1) { asm volatile("cp.async.wait_group 1;\n"); }
        else                  { asm volatile("cp.async.wait_group 0;\n"); }
        __syncthreads();

        if (kt + NSTG - 1 < KT) {
            int sl = sc + (NSTG - 1); if (sl >= NSTG) sl -= NSTG;
            const int ko = (kt + NSTG - 1)*16;
            const uint32_t sb = smem_u32 + (sl*STW)*4;
            cp16s(sb + dstw*4,          aH + ko);
            cp16s(sb + (SECW + dstw)*4, bH + ko);
            cp_commit();
        }

        const uint32_t sb = smem_u32 + (sc*STW)*4;

        uint32_t bhf[2][4];
        #pragma unroll
        for (int p = 0; p < 2; p++)
            ldsm4(bhf[p], sb + (SECW + boffw[p])*4);

        #pragma unroll
        for (int mt = 0; mt < 4; mt++) {
            uint32_t ahf[4];
            ldsm4(ahf, sb + (aoffw + mt*16*LDWW)*4);
            #pragma unroll
            for (int nt = 0; nt < 4; nt++) {
                const uint32_t* bp = &bhf[nt >> 1][(nt & 1)*2];
                mma_f16(acc[mt][nt], ahf, bp);
            }
        }
        sc = (sc + 1 == NSTG) ? 0 : sc + 1;
    }

    const int g = lane >> 2, t4 = lane & 3;
    float* Cb = C + (size_t)cRow*128*N + ccol*128;
    #pragma unroll
    for (int mt = 0; mt < 4; mt++) {
        const int r0 = warpM*64 + mt*16 + g;
        #pragma unroll
        for (int nt = 0; nt < 4; nt++) {
            const int c = warpN*32 + nt*8 + t4*2;
            *(float2*)&Cb[(size_t)r0 * N + c]       = make_float2(acc[mt][nt][0], acc[mt][nt][1]);
            *(float2*)&Cb[(size_t)(r0 + 8) * N + c] = make_float2(acc[mt][nt][2], acc[mt][nt][3]);
        }
    }
}

// ============================================================================
// hedgehog2 (R10/R11 measured config — separate q and k launches)
// ============================================================================
#define XS_STRIDE 260
#define FS_STRIDE 68
#define HG_SMEM ((64*XS_STRIDE + 64*FS_STRIDE + 128)*4)

__global__ __launch_bounds__(256, 2)
void hedgehog2_kernel(const float* __restrict__ x,
                      const float* __restrict__ cs,
                      const float* __restrict__ sn,
                      const float* __restrict__ fm,
                      float* __restrict__ outf,
                      int xh, float scale) {
    extern __shared__ float sm[];
    float* xs = sm;
    float* fs = sm + 64*XS_STRIDE;
    float* mz = fs + 64*FS_STRIDE;

    const int h = blockIdx.y, b = blockIdx.z;
    const int l0 = blockIdx.x * 64;
    const int t = threadIdx.x;
    const int srcH = (xh == 1) ? 0 : h;

    const float* xb = x + ((size_t)(b*L_ + l0)*xh + srcH)*HD_;
    const size_t xstride = (size_t)xh*HD_;
    #pragma unroll
    for (int p = 0; p < 16; p++) {
        int idx4 = p*256 + t;
        int r = idx4 >> 6, c4 = idx4 & 63;
        float4 v = *(const float4*)&xb[r*xstride + c4*4];
        *(float4*)&xs[r*XS_STRIDE + c4*4] = v;
    }
    __syncthreads();

    #pragma unroll
    for (int p = 0; p < 32; p++) {
        int e = p*256 + t;
        int r = e >> 7, j = e & 127;
        float c = cs[(l0 + r)*HALF_ + j];
        float s = sn[(l0 + r)*HALF_ + j];
        float x1 = xs[r*XS_STRIDE + j], x2 = xs[r*XS_STRIDE + j + 128];
        xs[r*XS_STRIDE + j]       = x1*c - x2*s;
        xs[r*XS_STRIDE + j + 128] = x1*s + x2*c;
    }
    __syncthreads();

    const int tr = t >> 4, tc = t & 15;
    float acc[4][4];
    #pragma unroll
    for (int i = 0; i < 4; i++)
        #pragma unroll
        for (int j = 0; j < 4; j++) acc[i][j] = 0.f;

    const float* fmh = fm + (size_t)h*HD_*FD_;
    for (int dt = 0; dt < 4; dt++) {
        #pragma unroll
        for (int p = 0; p < 4; p++) {
            int idx4 = p*256 + t;
            int r = idx4 >> 4, c4 = idx4 & 15;
            float4 v = *(const float4*)&fmh[(size_t)(dt*64 + r)*FD_ + c4*4];
            *(float4*)&fs[r*FS_STRIDE + c4*4] = v;
        }
        __syncthreads();

        #pragma unroll 4
        for (int dd = 0; dd < 64; dd += 4) {
            float4 xv[4], fv[4];
            #pragma unroll
            for (int i = 0; i < 4; i++)
                xv[i] = *(const float4*)&xs[(tr*4 + i)*XS_STRIDE + dt*64 + dd];
            #pragma unroll
            for (int k = 0; k < 4; k++)
                fv[k] = *(const float4*)&fs[(dd + k)*FS_STRIDE + tc*4];
            #pragma unroll
            for (int i = 0; i < 4; i++) {
                float* fvp0 = (float*)&fv[0];
                float* fvp1 = (float*)&fv[1];
                float* fvp2 = (float*)&fv[2];
                float* fvp3 = (float*)&fv[3];
                #pragma unroll
                for (int j = 0; j < 4; j++)
                    acc[i][j] += xv[i].x*fvp0[j] + xv[i].y*fvp1[j]
                               + xv[i].z*fvp2[j] + xv[i].w*fvp3[j];
            }
        }
        __syncthreads();
    }

    #pragma unroll
    for (int i = 0; i < 4; i++)
        *(float4*)&fs[(tr*4 + i)*FS_STRIDE + tc*4] =
            make_float4(acc[i][0], acc[i][1], acc[i][2], acc[i][3]);
    __syncthreads();

    const int warp = t >> 5, lane = t & 31;
    for (int rr = 0; rr < 8; rr++) {
        int rowi = warp*8 + rr;
        float v0 = fs[rowi*FS_STRIDE + lane];
        float v1 = fs[rowi*FS_STRIDE + lane + 32];
        float m = fmaxf(fabsf(v0), fabsf(v1));
        #pragma unroll
        for (int off = 16; off > 0; off >>= 1)
            m = fmaxf(m, __shfl_xor_sync(0xFFFFFFFF, m, off));
        float z = __expf(v0 - m) + __expf(-v0 - m)
                + __expf(v1 - m) + __expf(-v1 - m);
        #pragma unroll
        for (int off = 16; off > 0; off >>= 1)
            z += __shfl_xor_sync(0xFFFFFFFF, z, off);
        if (lane == 0) { mz[rowi] = m; mz[64 + rowi] = z; }
    }
    __syncthreads();

    float* ob = outf + ((size_t)(b*H_ + h)*L_ + l0)*FEAT_;
    #pragma unroll
    for (int p = 0; p < 8; p++) {
        int idx4 = p*256 + t;
        int rowi = idx4 >> 5, c4 = idx4 & 31;
        int f = c4*4;
        float m = mz[rowi], z = mz[64 + rowi];
        float inv = scale / z;
        float4 pv;
        if (f < 64) {
            pv = *(const float4*)&fs[rowi*FS_STRIDE + f];
            pv.x = __expf(pv.x - m)*inv; pv.y = __expf(pv.y - m)*inv;
            pv.z = __expf(pv.z - m)*inv; pv.w = __expf(pv.w - m)*inv;
        } else {
            pv = *(const float4*)&fs[rowi*FS_STRIDE + f - 64];
            pv.x = __expf(-pv.x - m)*inv; pv.y = __expf(-pv.y - m)*inv;
            pv.z = __expf(-pv.z - m)*inv; pv.w = __expf(-pv.w - m)*inv;
        }
        *(float4*)&ob[(size_t)rowi*FEAT_ + f] = pv;
    }
}

// ---------------- per-chunk kv state (register-tiled, R11 measured) --------
__global__ __launch_bounds__(256)
void kv2_kernel(const float* __restrict__ kf, const float* __restrict__ v,
                float* __restrict__ kv) {
    __shared__ float ks[32][FEAT_];
    __shared__ float vs[32][128];
    int n  = blockIdx.x;
    int dh = blockIdx.y;
    int bh = blockIdx.z;
    int b  = bh / H_;
    int t  = threadIdx.x;
    int tf = t >> 4;
    int td = t & 15;

    const float* kfp = kf + ((size_t)bh*L_ + n*CHUNK_)*FEAT_;
    const float* vp  = v  + ((size_t)b*L_  + n*CHUNK_)*HD_ + dh*128;

    float acc[8][8];
    #pragma unroll
    for (int i = 0; i < 8; i++)
        #pragma unroll
        for (int j = 0; j < 8; j++) acc[i][j] = 0.f;

    for (int cc = 0; cc < 2; cc++) {
        for (int e = t; e < 32*FEAT_; e += 256)
            ks[e >> 7][e & 127] = kfp[cc*32*FEAT_ + e];
        for (int e = t; e < 32*128; e += 256) {
            int r = e >> 7, c = e & 127;
            vs[r][c] = vp[(size_t)(cc*32 + r)*HD_ + c];
        }
        __syncthreads();

        #pragma unroll 4
        for (int c = 0; c < 32; c++) {
            float4 ka = *(const float4*)&ks[c][tf*8];
            float4 kb = *(const float4*)&ks[c][tf*8 + 4];
            float4 va = *(const float4*)&vs[c][td*4];
            float4 vb = *(const float4*)&vs[c][64 + td*4];
            float kk[8] = {ka.x,ka.y,ka.z,ka.w,kb.x,kb.y,kb.z,kb.w};
            float vv[8] = {va.x,va.y,va.z,va.w,vb.x,vb.y,vb.z,vb.w};
            #pragma unroll
            for (int i = 0; i < 8; i++)
                #pragma unroll
                for (int j = 0; j < 8; j++)
                    acc[i][j] += kk[i]*vv[j];
        }
        __syncthreads();
    }

    float* out = kv + ((size_t)(bh*NCH_ + n)*FEAT_)*HD_ + dh*128;
    #pragma unroll
    for (int i = 0; i < 8; i++) {
        size_t ro = (size_t)(tf*8 + i)*HD_;
        *(float4*)&out[ro + td*4]      = make_float4(acc[i][0], acc[i][1], acc[i][2], acc[i][3]);
        *(float4*)&out[ro + 64 + td*4] = make_float4(acc[i][4], acc[i][5], acc[i][6], acc[i][7]);
    }
}

// ---------------- exclusive cumsum: fp32 accumulate -> fp16 prefix out -----
// Thread handles an adjacent (d, d+1) element pair; writes half2.
__global__ void cumsum_kernel(const float* __restrict__ kv,
                              __half* __restrict__ kvh) {
    int bh = blockIdx.y;
    int e2 = (blockIdx.x*256 + threadIdx.x)*2;
    const float* base = kv  + (size_t)bh*NCH_*FEAT_*HD_ + e2;
    __half*      ob   = kvh + (size_t)bh*NCH_*FEAT_*HD_ + e2;
    float r0 = 0.f, r1 = 0.f;
    for (int n = 0; n < NCH_; n++) {
        float2 t = *(const float2*)&base[(size_t)n*FEAT_*HD_];
        *(__half2*)&ob[(size_t)n*FEAT_*HD_] = __floats2half2_rn(r0, r1);
        r0 += t.x; r1 += t.y;
    }
}

// ---------------- inter + intra chunk attention (fp16 kv prefix in,
//                  fp16 half2 output) --------------------------------------
__global__ __launch_bounds__(256)
void attn_kernel(const float* __restrict__ qf, const float* __restrict__ kf,
                 const float* __restrict__ v,  const __half* __restrict__ kvh,
                 __half* __restrict__ oh) {
    __shared__ float qs[CHUNK_][FEAT_];
    __shared__ float ss[CHUNK_][CHUNK_];
    int n = blockIdx.x, h = blockIdx.y, b = blockIdx.z;
    int bh = b*H_ + h;
    int t = threadIdx.x;
    const int c2 = (t & 127) * 2;
    const int rh = t >> 7;

    const float* qp = qf + ((size_t)bh*L_ + n*CHUNK_)*FEAT_;
    for (int e = t; e < CHUNK_*FEAT_; e += 256) qs[e/FEAT_][e%FEAT_] = qp[e];
    __syncthreads();

    float acc[32][2];
    #pragma unroll
    for (int i = 0; i < 32; i++) { acc[i][0] = 0.f; acc[i][1] = 0.f; }

    // Phase A: inter = q @ KVprev (fp16 prefix, half2 loads)
    const __half* kvp = kvh + ((size_t)(bh*NCH_ + n)*FEAT_)*HD_;
    for (int f = 0; f < FEAT_; f += 4) {
        float2 k0 = __half22float2(*(const __half2*)&kvp[(size_t)(f+0)*HD_ + c2]);
        float2 k1 = __half22float2(*(const __half2*)&kvp[(size_t)(f+1)*HD_ + c2]);
        float2 k2 = __half22float2(*(const __half2*)&kvp[(size_t)(f+2)*HD_ + c2]);
        float2 k3 = __half22float2(*(const __half2*)&kvp[(size_t)(f+3)*HD_ + c2]);
        #pragma unroll
        for (int i = 0; i < 32; i++) {
            float4 qv = *(const float4*)&qs[rh*32 + i][f];
            acc[i][0] += qv.x*k0.x + qv.y*k1.x + qv.z*k2.x + qv.w*k3.x;
            acc[i][1] += qv.x*k0.y + qv.y*k1.y + qv.z*k2.y + qv.w*k3.y;
        }
    }

    // Phase B: s = tril(q @ k^T)
    {
        const float* kp = kf + ((size_t)bh*L_ + n*CHUNK_)*FEAT_;
        int i   = t / 4;
        int jp0 = (t % 4) * 16;
        for (int jj = 0; jj < 16; jj++) {
            int jp = jp0 + jj;
            float sum = 0.f;
            if (jp <= i) {
                const float* krow = kp + (size_t)jp*FEAT_;
                #pragma unroll 8
                for (int f = 0; f < FEAT_; f += 4) {
                    float4 qv = *(const float4*)&qs[i][f];
                    float4 kr = *(const float4*)&krow[f];
                    sum += qv.x*kr.x + qv.y*kr.y + qv.z*kr.z + qv.w*kr.w;
                }
            }
            ss[i][jp] = sum;
        }
    }
    __syncthreads();

    // Phase C: intra = s @ v
    const float* vp = v + ((size_t)b*L_ + n*CHUNK_)*HD_;
    for (int jp = 0; jp < CHUNK_; jp += 4) {
        float2 v0 = *(const float2*)&vp[(size_t)(jp+0)*HD_ + c2];
        float2 v1 = *(const float2*)&vp[(size_t)(jp+1)*HD_ + c2];
        float2 v2 = *(const float2*)&vp[(size_t)(jp+2)*HD_ + c2];
        float2 v3 = *(const float2*)&vp[(size_t)(jp+3)*HD_ + c2];
        #pragma unroll
        for (int i = 0; i < 32; i++) {
            float4 sv = *(const float4*)&ss[rh*32 + i][jp];
            acc[i][0] += sv.x*v0.x + sv.y*v1.x + sv.z*v2.x + sv.w*v3.x;
            acc[i][1] += sv.x*v0.y + sv.y*v1.y + sv.z*v2.y + sv.w*v3.y;
        }
    }

    __half* op = oh + ((size_t)(b*L_ + n*CHUNK_ + rh*32))*(H_*HD_) + h*HD_ + c2;
    #pragma unroll
    for (int i = 0; i < 32; i++)
        *(__half2*)&op[(size_t)i*(H_*HD_)] = __floats2half2_rn(acc[i][0], acc[i][1]);
}

// ---------------- launch ---------------------------------------------------
extern "C" void kernel_launch(void* const* d_in, const int* in_sizes, int n_in,
                              void* d_out, int out_size) {
    const float* hidden = (const float*)d_in[0];
    const float* fcos   = (const float*)d_in[1];
    const float* fsin   = (const float*)d_in[2];
    // d_in[3] = mask (unused)
    const float* Wq     = (const float*)d_in[4];
    const float* Wk     = (const float*)d_in[5];
    const float* Wv     = (const float*)d_in[6];
    const float* Wo     = (const float*)d_in[7];
    const float* fmq    = (const float*)d_in[8];
    const float* fmk    = (const float*)d_in[9];
    float* out          = (float*)d_out;

    float *q, *k, *v, *qf, *kf, *kv;
    cudaGetSymbolAddress((void**)&q,  g_q);
    cudaGetSymbolAddress((void**)&k,  g_k);
    cudaGetSymbolAddress((void**)&v,  g_v);
    cudaGetSymbolAddress((void**)&qf, g_qf);
    cudaGetSymbolAddress((void**)&kf, g_kf);
    cudaGetSymbolAddress((void**)&kv, g_kv);

    __half *kvh,*hh,*oh,*wqh,*wkh,*wvh,*woh;
    cudaGetSymbolAddress((void**)&kvh, g_kvh);
    cudaGetSymbolAddress((void**)&hh,  g_hh);
    cudaGetSymbolAddress((void**)&oh,  g_oh);
    cudaGetSymbolAddress((void**)&wqh, g_wqh);
    cudaGetSymbolAddress((void**)&wkh, g_wkh);
    cudaGetSymbolAddress((void**)&wvh, g_wvh);
    cudaGetSymbolAddress((void**)&woh, g_woh);

    cudaFuncSetAttribute(hgemm_kernel,
                         cudaFuncAttributeMaxDynamicSharedMemorySize, SMEM_BYTES);
    cudaFuncSetAttribute(hedgehog2_kernel,
                         cudaFuncAttributeMaxDynamicSharedMemorySize, HG_SMEM);

    const int M = B_*L_;   // 4096
    const float qscale = 0.08838834764831845f;   // 128^-0.5
    const int halfN = (M*D_)/2;

    // 0: all weight transposes
    splitT_all_kernel<<<dim3(64, 64, 4), 256>>>(Wq, wqh, Wo, woh, Wk, wkh, Wv, wvh);
    // 1,2: convert hidden -> fp16 (two halves)
    cvt_kernel<<<halfN/2048, 256>>>(hidden, hh, 0,     halfN);
    cvt_kernel<<<halfN/2048, 256>>>(hidden, hh, halfN, halfN);
    // 3: fused Q+K+V projections (PROFILED slot)
    hgemm_kernel<<<dim3(20, M/128), 256, SMEM_BYTES>>>(M, D_, 16, 2,
        hh, wqh, q, H_*HD_, wkh, k, wvh, v);
    // 4: hedgehog q (fused RoPE)
    hedgehog2_kernel<<<dim3(L_/64, H_, B_), 256, HG_SMEM>>>(q, fcos, fsin, fmq, qf, H_, qscale);
    // 5: hedgehog k
    hedgehog2_kernel<<<dim3(L_/64, H_, B_), 256, HG_SMEM>>>(k, fcos, fsin, fmk, kf, 1, 1.0f);
    // 6: per-chunk kv states
    kv2_kernel<<<dim3(NCH_, 2, B_*H_), 256>>>(kf, v, kv);
    // 7: exclusive cumsum (fp32 accumulate -> fp16 prefix)
    cumsum_kernel<<<dim3(64, B_*H_), 256>>>(kv, kvh);
    // 8: inter + intra attention -> fp16 oh
    attn_kernel<<<dim3(NCH_, H_, B_), 256>>>(qf, kf, v, kvh, oh);
    // 9: output projection
    hgemm_kernel<<<dim3(16, M/128), 256, SMEM_BYTES>>>(M, H_*HD_, 16, 0,
        oh, woh, out, D_, woh, out, woh, out);
}